// round 12
// baseline (speedup 1.0000x reference)
#include <cuda_runtime.h>
#include <cstddef>

#define NT 10240
#define KG 20
#define MG 512

typedef unsigned long long u64;

// ---- scratch (device globals; allocation is forbidden) ----
__device__ float g_hlast[NT * 64];
__device__ float g_hatt[NT * 64];
__device__ float g_hfc[NT * 64];   // layout [m][K][64]
__device__ float g_z[NT * 64];     // layout [m][K][64]
__device__ float g_r[NT * 64];     // layout [m][K][64]
__device__ float g_vec[130];       // v_dst[64] | v_src[64] | c_dst | c_src

__device__ __forceinline__ float sige(float v) {
    return __fdividef(1.f, 1.f + __expf(-v));
}
// tanh(x) = 1 - 2/(e^{2x}+1); NaN-safe at +/-inf, rel err ~1e-6
__device__ __forceinline__ float tanhe(float v) {
    return 1.f - __fdividef(2.f, __expf(2.f * v) + 1.f);
}
__device__ __forceinline__ float lrelu(float v) { return v > 0.f ? v : 0.01f * v; }

__device__ __forceinline__ void fma2(u64& d, u64 a, u64 b) {
    asm("fma.rn.f32x2 %0, %1, %2, %3;" : "=l"(d) : "l"(a), "l"(b), "l"(d));
}
__device__ __forceinline__ u64 pack2(float lo, float hi) {
    u64 r;
    asm("mov.b64 %0, {%1, %2};" : "=l"(r) : "f"(lo), "f"(hi));
    return r;
}
__device__ __forceinline__ float upk(u64 a, float bias) {
    float lo = __uint_as_float((unsigned)(a & 0xffffffffu));
    float hi = __uint_as_float((unsigned)(a >> 32));
    return lo + hi + bias;
}
__device__ __forceinline__ float u64lo(u64 a) { return __uint_as_float((unsigned)(a & 0xffffffffu)); }
__device__ __forceinline__ float u64hi(u64 a) { return __uint_as_float((unsigned)(a >> 32)); }

// ============================================================================
// ENCODER: fused 2-layer GRU, gates fully in registers.
// 384 threads = 12 warps (3/SMSP for latency hiding); warp = SPG=6 samples.
// Lane og owns outputs o = j*32+og, j=0..5.
// ============================================================================

template <int SPG, int KDIM, bool ACCRZ>
__device__ __forceinline__ void gemm_pass(const float* __restrict__ inp,
                                          const float* __restrict__ Wp,
                                          u64 (&aRZ)[SPG][4], u64 (&aN)[SPG][2],
                                          int og, int sg)
{
    const u64* W2 = reinterpret_cast<const u64*>(Wp);
    const u64* I2 = reinterpret_cast<const u64*>(inp);
#pragma unroll
    for (int p = 0; p < SPG; p++) {
        if (!ACCRZ) { aRZ[p][0] = 0; aRZ[p][1] = 0; aRZ[p][2] = 0; aRZ[p][3] = 0; }
        aN[p][0] = 0; aN[p][1] = 0;
    }
#pragma unroll 4
    for (int k2 = 0; k2 < KDIM / 2; k2++) {
        u64 w[6];
#pragma unroll
        for (int j = 0; j < 6; j++) w[j] = W2[(k2 * 6 + j) * 32 + og];
#pragma unroll
        for (int p = 0; p < SPG; p++) {
            u64 a = I2[(sg * SPG + p) * (KDIM / 2) + k2];
            fma2(aRZ[p][0], a, w[0]);
            fma2(aRZ[p][1], a, w[1]);
            fma2(aRZ[p][2], a, w[2]);
            fma2(aRZ[p][3], a, w[3]);
            fma2(aN[p][0], a, w[4]);
            fma2(aN[p][1], a, w[5]);
        }
    }
}

template <int SPG>
__device__ __forceinline__ void gemm_dual(const float* __restrict__ inA,
                                          const float* __restrict__ inB,
                                          const float* __restrict__ WA,
                                          const float* __restrict__ WB,
                                          u64 (&aRZ)[SPG][4], u64 (&aNI)[SPG][2],
                                          u64 (&aNH)[SPG][2], int og, int sg)
{
    const u64* WA2 = reinterpret_cast<const u64*>(WA);
    const u64* WB2 = reinterpret_cast<const u64*>(WB);
    const u64* IA2 = reinterpret_cast<const u64*>(inA);
    const u64* IB2 = reinterpret_cast<const u64*>(inB);
#pragma unroll
    for (int p = 0; p < SPG; p++) {
        aRZ[p][0] = 0; aRZ[p][1] = 0; aRZ[p][2] = 0; aRZ[p][3] = 0;
        aNI[p][0] = 0; aNI[p][1] = 0; aNH[p][0] = 0; aNH[p][1] = 0;
    }
#pragma unroll 2
    for (int k2 = 0; k2 < 32; k2++) {
        u64 wa[6], wb[6];
#pragma unroll
        for (int j = 0; j < 6; j++) {
            wa[j] = WA2[(k2 * 6 + j) * 32 + og];
            wb[j] = WB2[(k2 * 6 + j) * 32 + og];
        }
#pragma unroll
        for (int p = 0; p < SPG; p++) {
            u64 a = IA2[(sg * SPG + p) * 32 + k2];
            u64 b = IB2[(sg * SPG + p) * 32 + k2];
            fma2(aRZ[p][0], a, wa[0]); fma2(aRZ[p][0], b, wb[0]);
            fma2(aRZ[p][1], a, wa[1]); fma2(aRZ[p][1], b, wb[1]);
            fma2(aRZ[p][2], a, wa[2]); fma2(aRZ[p][2], b, wb[2]);
            fma2(aRZ[p][3], a, wa[3]); fma2(aRZ[p][3], b, wb[3]);
            fma2(aNI[p][0], a, wa[4]); fma2(aNI[p][1], a, wa[5]);
            fma2(aNH[p][0], b, wb[4]); fma2(aNH[p][1], b, wb[5]);
        }
    }
}

template <int SPG, int NTHR>
__global__ void __launch_bounds__(NTHR, 1)
enc_kernel(const float* __restrict__ x,
           const float* __restrict__ Wih0, const float* __restrict__ Whh0,
           const float* __restrict__ bih0, const float* __restrict__ bhh0,
           const float* __restrict__ Wih1, const float* __restrict__ Whh1,
           const float* __restrict__ bih1, const float* __restrict__ bhh1,
           float* __restrict__ out, int T)
{
    constexpr int NW = NTHR / 32;
    constexpr int S = NW * SPG;
    extern __shared__ float sm[];
    float* sWih0p = sm;                      // [3*6*64]   K=6 paired
    float* sWhh0p = sWih0p + 1152;           // [32*6*64]  paired
    float* sWih1p = sWhh0p + 12288;
    float* sWhh1p = sWih1p + 12288;
    float* sbrz0  = sWhh1p + 12288;          // [128] bih0+bhh0 (r,z)
    float* sbni0  = sbrz0 + 128;             // [64]
    float* sbnh0  = sbni0 + 64;              // [64]
    float* sbrz1  = sbnh0 + 64;              // [128]
    float* sbni1  = sbrz1 + 128;
    float* sbnh1  = sbni1 + 64;
    float* sh0    = sbnh1 + 64;              // [2][S*64] double buffered
    float* sh1    = sh0 + 2 * S * 64;        // [S*64]
    float* sxt    = sh1 + S * 64;            // [2][S*6]

    const int tid = threadIdx.x;
    const int base = blockIdx.x * S;

    for (int idx = tid; idx < 12288; idx += NTHR) {
        int og2 = idx & 63;
        int j = (idx >> 6) % 6;
        int k2 = idx / 384;
        int o = j * 32 + (og2 >> 1);
        int k = k2 * 2 + (og2 & 1);
        sWhh0p[idx] = Whh0[o * 64 + k];
        sWih1p[idx] = Wih1[o * 64 + k];
        sWhh1p[idx] = Whh1[o * 64 + k];
    }
    for (int idx = tid; idx < 1152; idx += NTHR) {
        int og2 = idx & 63;
        int j = (idx >> 6) % 6;
        int k2 = idx / 384;     // < 3
        int o = j * 32 + (og2 >> 1);
        int k = k2 * 2 + (og2 & 1);
        sWih0p[idx] = Wih0[o * 6 + k];
    }
    if (tid < 128) {
        sbrz0[tid] = bih0[tid] + bhh0[tid];
        sbrz1[tid] = bih1[tid] + bhh1[tid];
    } else if (tid < 192) {
        int d = tid - 128;
        sbni0[d] = bih0[128 + d]; sbnh0[d] = bhh0[128 + d];
        sbni1[d] = bih1[128 + d]; sbnh1[d] = bhh1[128 + d];
    }
    for (int idx = tid; idx < 2 * S * 64; idx += NTHR) sh0[idx] = 0.f;
    for (int idx = tid; idx < S * 64; idx += NTHR) sh1[idx] = 0.f;
    for (int idx = tid; idx < S * 6; idx += NTHR) {
        int s = idx / 6, i = idx % 6;
        int gs = base + s;
        sxt[idx] = (gs < NT) ? x[((size_t)gs * T) * 6 + i] : 0.f;
    }
    __syncthreads();

    const int og = tid & 31, sg = tid >> 5;
    constexpr int XN = S * 6;
    constexpr int XR = (XN + NTHR - 1) / NTHR;

    u64 aRZ[SPG][4], aNI[SPG][2], aNH[SPG][2];
    float hn0[SPG], hn1[SPG];

    for (int t = 0; t < T; t++) {
        const int cur = t & 1, nxt = cur ^ 1;

        float xr[XR];
        if (t + 1 < T) {
#pragma unroll
            for (int r = 0; r < XR; r++) {
                int idx = tid + r * NTHR;
                if (idx < XN) {
                    int s = idx / 6, i = idx % 6;
                    int gs = base + s;
                    xr[r] = (gs < NT) ? x[((size_t)gs * T + t + 1) * 6 + i] : 0.f;
                }
            }
        }

        // -------- layer 0 --------
        gemm_pass<SPG, 6, false>(sxt + cur * XN, sWih0p, aRZ, aNI, og, sg);
        gemm_pass<SPG, 64, true>(sh0 + cur * S * 64, sWhh0p, aRZ, aNH, og, sg);
#pragma unroll
        for (int p = 0; p < SPG; p++) {
            int s = sg * SPG + p;
            float r0 = sige(upk(aRZ[p][0], sbrz0[og]));
            float r1 = sige(upk(aRZ[p][1], sbrz0[32 + og]));
            float z0 = sige(upk(aRZ[p][2], sbrz0[64 + og]));
            float z1 = sige(upk(aRZ[p][3], sbrz0[96 + og]));
            float n0 = tanhe(upk(aNI[p][0], sbni0[og]) + r0 * upk(aNH[p][0], sbnh0[og]));
            float n1 = tanhe(upk(aNI[p][1], sbni0[32 + og]) + r1 * upk(aNH[p][1], sbnh0[32 + og]));
            float hp0 = sh0[cur * S * 64 + s * 64 + og];
            float hp1 = sh0[cur * S * 64 + s * 64 + 32 + og];
            hn0[p] = n0 + z0 * (hp0 - n0);
            hn1[p] = n1 + z1 * (hp1 - n1);
        }
#pragma unroll
        for (int p = 0; p < SPG; p++) {
            int s = sg * SPG + p;
            sh0[nxt * S * 64 + s * 64 + og] = hn0[p];
            sh0[nxt * S * 64 + s * 64 + 32 + og] = hn1[p];
        }
        if (t + 1 < T) {
#pragma unroll
            for (int r = 0; r < XR; r++) {
                int idx = tid + r * NTHR;
                if (idx < XN) sxt[nxt * XN + idx] = xr[r];
            }
        }
        __syncthreads();   // B1

        // -------- layer 1: fused dual GEMM + EW --------
        gemm_dual<SPG>(sh0 + nxt * S * 64, sh1, sWih1p, sWhh1p, aRZ, aNI, aNH, og, sg);
#pragma unroll
        for (int p = 0; p < SPG; p++) {
            int s = sg * SPG + p;
            float r0 = sige(upk(aRZ[p][0], sbrz1[og]));
            float r1 = sige(upk(aRZ[p][1], sbrz1[32 + og]));
            float z0 = sige(upk(aRZ[p][2], sbrz1[64 + og]));
            float z1 = sige(upk(aRZ[p][3], sbrz1[96 + og]));
            float n0 = tanhe(upk(aNI[p][0], sbni1[og]) + r0 * upk(aNH[p][0], sbnh1[og]));
            float n1 = tanhe(upk(aNI[p][1], sbni1[32 + og]) + r1 * upk(aNH[p][1], sbnh1[32 + og]));
            float hp0 = sh1[s * 64 + og];
            float hp1 = sh1[s * 64 + 32 + og];
            hn0[p] = n0 + z0 * (hp0 - n0);
            hn1[p] = n1 + z1 * (hp1 - n1);
        }
        if (t == T - 1) {
#pragma unroll
            for (int p = 0; p < SPG; p++) {
                int gs = base + sg * SPG + p;
                if (gs < NT) {
                    out[(size_t)gs * 64 + og] = hn0[p];
                    out[(size_t)gs * 64 + 32 + og] = hn1[p];
                }
            }
        }
        __syncthreads();   // B2
#pragma unroll
        for (int p = 0; p < SPG; p++) {
            int s = sg * SPG + p;
            sh1[s * 64 + og] = hn0[p];
            sh1[s * 64 + 32 + og] = hn1[p];
        }
    }
}

// ============================================================================
// ALSTM: j-split 2-layer GRU (unchanged from R10 passing kernel).
// ============================================================================
__global__ void __launch_bounds__(256, 1)
alstm_kernel(const float* __restrict__ zin,
             const float* __restrict__ Wih0, const float* __restrict__ Whh0,
             const float* __restrict__ bih0, const float* __restrict__ bhh0,
             const float* __restrict__ Wih1, const float* __restrict__ Whh1,
             const float* __restrict__ bih1, const float* __restrict__ bhh1,
             float* __restrict__ outr, int T)
{
    extern __shared__ float sm[];
    float* sW0   = sm;                 // [24576]
    float* sW1   = sW0 + 24576;        // [24576]
    float* sbrz0 = sW1 + 24576;        // [128]
    float* sbni0 = sbrz0 + 128;        // [64]
    float* sbnh0 = sbni0 + 64;
    float* sbrz1 = sbnh0 + 64;         // [128]
    float* sbni1 = sbrz1 + 128;
    float* sbnh1 = sbni1 + 64;         // biases end at +512
    float* sh0   = sbnh1 + 64;         // [2][256]
    float* sh1   = sh0 + 512;          // [256]
    float* sxt   = sh1 + 256;          // [2][256]
    float* sgA   = sxt + 512;          // [4][256]  layer0 gates
    float* sgB   = sgA + 1024;         // [4][256]  layer1 gates

    const int tid = threadIdx.x;
    const int base = blockIdx.x * 4;

    for (int idx = tid; idx < 24576; idx += 256) {
        int og2 = idx & 63;
        int col = idx >> 6;            // k2*12 + j*2 + src
        int src = col & 1;
        int j = (col >> 1) % 6;
        int k2 = col / 12;
        int o = j * 32 + (og2 >> 1);
        int k = k2 * 2 + (og2 & 1);
        sW0[idx] = src ? Whh0[o * 64 + k] : Wih0[o * 64 + k];
        sW1[idx] = src ? Whh1[o * 64 + k] : Wih1[o * 64 + k];
    }
    if (tid < 128) {
        sbrz0[tid] = bih0[tid] + bhh0[tid];
        sbrz1[tid] = bih1[tid] + bhh1[tid];
    } else if (tid < 192) {
        int d = tid - 128;
        sbni0[d] = bih0[128 + d]; sbnh0[d] = bhh0[128 + d];
        sbni1[d] = bih1[128 + d]; sbnh1[d] = bhh1[128 + d];
    }
    for (int idx = tid; idx < 512; idx += 256) sh0[idx] = 0.f;
    sh1[tid] = 0.f;
    {
        int s = tid >> 6, d = tid & 63;
        sxt[tid] = zin[((size_t)(base + s) * T) * 64 + d];
    }
    __syncthreads();

    const int og = tid & 31;
    const int w = tid >> 5;

    const u64* W02 = reinterpret_cast<const u64*>(sW0);
    const u64* W12 = reinterpret_cast<const u64*>(sW1);

    for (int t = 0; t < T; t++) {
        const int cur = t & 1, nxt = cur ^ 1;

        float xpre = 0.f;
        if (t + 1 < T) {
            int s = tid >> 6, d = tid & 63;
            xpre = zin[((size_t)(base + s) * T + t + 1) * 64 + d];
        }

        // ---- layer 0 GEMM (warps 0-5) ----
        if (w < 6) {
            const u64* X2 = reinterpret_cast<const u64*>(sxt + cur * 256);
            const u64* H2 = reinterpret_cast<const u64*>(sh0 + cur * 256);
            u64 aI[4] = {0, 0, 0, 0}, aH[4] = {0, 0, 0, 0};
#pragma unroll 4
            for (int k2 = 0; k2 < 32; k2++) {
                u64 wI = W02[(k2 * 12 + w * 2) * 32 + og];
                u64 wH = W02[(k2 * 12 + w * 2 + 1) * 32 + og];
#pragma unroll
                for (int s = 0; s < 4; s++) {
                    fma2(aI[s], X2[s * 32 + k2], wI);
                    fma2(aH[s], H2[s * 32 + k2], wH);
                }
            }
#pragma unroll
            for (int s = 0; s < 4; s++) {
                if (w < 4) {
                    sgA[s * 256 + w * 32 + og] = upk(aI[s], 0.f) + upk(aH[s], sbrz0[w * 32 + og]);
                } else {
                    sgA[s * 256 + 128 + (w - 4) * 32 + og] = upk(aI[s], sbni0[(w - 4) * 32 + og]);
                    sgA[s * 256 + 192 + (w - 4) * 32 + og] = upk(aH[s], sbnh0[(w - 4) * 32 + og]);
                }
            }
        }
        if (t + 1 < T) sxt[nxt * 256 + tid] = xpre;
        __syncthreads();   // B1

        // ---- layer 0 EW (warps 0-3, warp = sample) ----
        if (w < 4) {
            const float* g = sgA + w * 256;
            float r0 = sige(g[og]),       r1 = sige(g[32 + og]);
            float z0 = sige(g[64 + og]),  z1 = sige(g[96 + og]);
            float n0 = tanhe(g[128 + og] + r0 * g[192 + og]);
            float n1 = tanhe(g[160 + og] + r1 * g[224 + og]);
            float hp0 = sh0[cur * 256 + w * 64 + og];
            float hp1 = sh0[cur * 256 + w * 64 + 32 + og];
            sh0[nxt * 256 + w * 64 + og]      = n0 + z0 * (hp0 - n0);
            sh0[nxt * 256 + w * 64 + 32 + og] = n1 + z1 * (hp1 - n1);
        }
        __syncthreads();   // B2

        // ---- layer 1 GEMM (warps 0-5) ----
        if (w < 6) {
            const u64* X2 = reinterpret_cast<const u64*>(sh0 + nxt * 256);
            const u64* H2 = reinterpret_cast<const u64*>(sh1);
            u64 aI[4] = {0, 0, 0, 0}, aH[4] = {0, 0, 0, 0};
#pragma unroll 4
            for (int k2 = 0; k2 < 32; k2++) {
                u64 wI = W12[(k2 * 12 + w * 2) * 32 + og];
                u64 wH = W12[(k2 * 12 + w * 2 + 1) * 32 + og];
#pragma unroll
                for (int s = 0; s < 4; s++) {
                    fma2(aI[s], X2[s * 32 + k2], wI);
                    fma2(aH[s], H2[s * 32 + k2], wH);
                }
            }
#pragma unroll
            for (int s = 0; s < 4; s++) {
                if (w < 4) {
                    sgB[s * 256 + w * 32 + og] = upk(aI[s], 0.f) + upk(aH[s], sbrz1[w * 32 + og]);
                } else {
                    sgB[s * 256 + 128 + (w - 4) * 32 + og] = upk(aI[s], sbni1[(w - 4) * 32 + og]);
                    sgB[s * 256 + 192 + (w - 4) * 32 + og] = upk(aH[s], sbnh1[(w - 4) * 32 + og]);
                }
            }
        }
        __syncthreads();   // B3

        // ---- layer 1 EW + output (warps 0-3) ----
        if (w < 4) {
            const float* g = sgB + w * 256;
            float r0 = sige(g[og]),       r1 = sige(g[32 + og]);
            float z0 = sige(g[64 + og]),  z1 = sige(g[96 + og]);
            float n0 = tanhe(g[128 + og] + r0 * g[192 + og]);
            float n1 = tanhe(g[160 + og] + r1 * g[224 + og]);
            float hp0 = sh1[w * 64 + og];
            float hp1 = sh1[w * 64 + 32 + og];
            float h0n = n0 + z0 * (hp0 - n0);
            float h1n = n1 + z1 * (hp1 - n1);
            outr[((size_t)(base + w) * T + t) * 64 + og]      = h0n;
            outr[((size_t)(base + w) * T + t) * 64 + 32 + og] = h1n;
            sh1[w * 64 + og] = h0n;
            sh1[w * 64 + 32 + og] = h1n;
        }
        // safe: next readers of sh1 (layer-1 GEMM of t+1) sit behind B1+B2
    }
}

// v_dst = trans_W^T a[:64], v_src = trans_W^T a[64:], plus bias dots.
__global__ void prep_kernel(const float* __restrict__ tW, const float* __restrict__ tb,
                            const float* __restrict__ a)
{
    int d = threadIdx.x;  // 64 threads
    float vd = 0.f, vs = 0.f;
    for (int o = 0; o < 64; o++) {
        vd = fmaf(tW[o * 64 + d], a[o], vd);
        vs = fmaf(tW[o * 64 + d], a[64 + o], vs);
    }
    g_vec[d] = vd; g_vec[64 + d] = vs;
    if (d == 0) {
        float cd = 0.f, cs = 0.f;
        for (int o = 0; o < 64; o++) { cd = fmaf(tb[o], a[o], cd); cs = fmaf(tb[o], a[64 + o], cs); }
        g_vec[128] = cd; g_vec[129] = cs;
    }
}

// Dense GAT: per-node scores (fused) + attention + aggregate + residual.
// grid = KG*4 (group x 128-row chunk). R5 inner loop; ew buffer 1024/warp.
__global__ void att_kernel()
{
    extern __shared__ float sm[];
    float* sh  = sm;                 // [512*64] plain rows
    float* sd  = sm + 32768;         // [512] s_dst
    float* ssc = sd + 512;           // [512] s_src
    float* sv  = ssc + 512;          // [132]
    float* se  = sv + 132;           // [8 warps][8 rows][128] exp rows
    int k = blockIdx.x >> 2, chunk = blockIdx.x & 3;
    int tid = threadIdx.x, l = tid & 31, w = tid >> 5;
    const float* hg = g_hlast + (size_t)k * 512 * 64;
    for (int i = tid; i < 32768; i += 256) sh[i] = hg[i];
    if (tid < 130) sv[tid] = g_vec[tid];
    __syncthreads();

    // scores for all 512 nodes: warp w owns nodes [w*64, w*64+64)
    for (int i = 0; i < 64; i++) {
        int n = w * 64 + i;
        float h0 = sh[n * 64 + l], h1 = sh[n * 64 + 32 + l];
        float ps = h0 * sv[64 + l] + h1 * sv[96 + l];
        float pd = h0 * sv[l] + h1 * sv[32 + l];
#pragma unroll
        for (int off = 16; off; off >>= 1) {
            ps += __shfl_xor_sync(~0u, ps, off);
            pd += __shfl_xor_sync(~0u, pd, off);
        }
        if (l == 0) { ssc[n] = ps + sv[129]; sd[n] = pd + sv[128]; }
    }
    __syncthreads();

    // group max of s_dst (lrelu monotone -> row max = lrelu(s_src_i + dmax))
    float dm = -1e30f;
    for (int i = l; i < 512; i += 32) dm = fmaxf(dm, sd[i]);
#pragma unroll
    for (int off = 16; off; off >>= 1) dm = fmaxf(dm, __shfl_xor_sync(~0u, dm, off));

    const u64* sh2 = reinterpret_cast<const u64*>(sh);
    float* ew = se + w * 1024;

    for (int batch = 0; batch < 2; batch++) {
        int b0 = chunk * 128 + w * 16 + batch * 8;
        float si[8], mi[8], den[8];
        u64 acc[8];
#pragma unroll
        for (int i = 0; i < 8; i++) {
            si[i] = ssc[b0 + i];
            mi[i] = lrelu(si[i] + dm);
            den[i] = 0.f; acc[i] = 0ull;
        }
        for (int jt = 0; jt < 4; jt++) {
#pragma unroll
            for (int i = 0; i < 8; i++) {
#pragma unroll
                for (int q = 0; q < 4; q++) {
                    int j = jt * 128 + q * 32 + l;
                    float e = __expf(lrelu(si[i] + sd[j]) - mi[i]);
                    ew[i * 128 + q * 32 + l] = e;
                    den[i] += e;
                }
            }
            __syncwarp();
#pragma unroll 4
            for (int j0 = 0; j0 < 128; j0++) {
                int j = jt * 128 + j0;
                u64 hv = sh2[j * 32 + l];
#pragma unroll
                for (int i = 0; i < 8; i++) {
                    u64 e2 = (u64)__float_as_uint(ew[i * 128 + j0]);
                    e2 |= e2 << 32;
                    fma2(acc[i], e2, hv);
                }
            }
            __syncwarp();
        }
#pragma unroll
        for (int i = 0; i < 8; i++) {
            float d = den[i];
#pragma unroll
            for (int off = 16; off; off >>= 1) d += __shfl_xor_sync(~0u, d, off);
            float inv = __fdividef(1.f, d);
            int r = b0 + i;
            float* o = g_hatt + ((size_t)k * 512 + r) * 64;
            o[2 * l]     = fmaf(u64lo(acc[i]), inv, sh[r * 64 + 2 * l]);
            o[2 * l + 1] = fmaf(u64hi(acc[i]), inv, sh[r * 64 + 2 * l + 1]);
        }
    }
}

// hfc = hatt @ fc_W^T + fc_b ([m][K][64] layout); z = tanh(hfc @ al_in_W^T + al_in_b).
__global__ void fc_kernel(const float* __restrict__ fcW, const float* __restrict__ fcb,
                          const float* __restrict__ inW, const float* __restrict__ inb)
{
    __shared__ float sWf[64 * 64], sWi[64 * 64], sbf[64], sbi[64];
    __shared__ u64 sr2[8][64], sf2[8][64];
    int tid = threadIdx.x;
    for (int i = tid; i < 4096; i += 256) {
        int o = i >> 6, d = i & 63;
        sWf[d * 64 + o] = fcW[i];
        sWi[d * 64 + o] = inW[i];
    }
    if (tid < 64) { sbf[tid] = fcb[tid]; sbi[tid] = inb[tid]; }
    __syncthreads();
    const u64* sWf2 = reinterpret_cast<const u64*>(sWf);
    const u64* sWi2 = reinterpret_cast<const u64*>(sWi);
    int w = tid >> 5, l = tid & 31;
    for (int it = 0; it < 16; it++) {
        int n = blockIdx.x * 128 + it * 8 + w;  // 80*128 = 10240
        const float* hr = g_hatt + (size_t)n * 64;
        float v0 = hr[l], v1 = hr[l + 32];
        sr2[w][l] = pack2(v0, v0); sr2[w][l + 32] = pack2(v1, v1);
        __syncwarp();
        u64 acc = 0ull;
#pragma unroll 4
        for (int d = 0; d < 64; d++)
            fma2(acc, sr2[w][d], sWf2[d * 32 + l]);
        float a0 = u64lo(acc) + sbf[2 * l];
        float a1 = u64hi(acc) + sbf[2 * l + 1];
        int kk = n >> 9, ii = n & 511;
        float* of = g_hfc + ((size_t)ii * KG + kk) * 64;
        *reinterpret_cast<u64*>(&of[2 * l]) = pack2(a0, a1);
        sf2[w][2 * l] = pack2(a0, a0); sf2[w][2 * l + 1] = pack2(a1, a1);
        __syncwarp();
        u64 acc2 = 0ull;
#pragma unroll 4
        for (int d = 0; d < 64; d++)
            fma2(acc2, sf2[w][d], sWi2[d * 32 + l]);
        float z0 = tanhe(u64lo(acc2) + sbi[2 * l]);
        float z1 = tanhe(u64hi(acc2) + sbi[2 * l + 1]);
        float* oz = g_z + ((size_t)ii * KG + kk) * 64;
        *reinterpret_cast<u64*>(&oz[2 * l]) = pack2(z0, z1);
        __syncwarp();
    }
}

// ALSTM attention head + final outputs. Warp per sample. grid = 64.
__global__ void head_kernel(const float* __restrict__ W1, const float* __restrict__ b1,
                            const float* __restrict__ W2,
                            const float* __restrict__ Wo, const float* __restrict__ bo,
                            const float* __restrict__ fcoW, const float* __restrict__ fcob,
                            float* __restrict__ out)
{
    __shared__ float sW1[64 * 32], sb1[32], sW2[32], sWo[128], sfw[64];
    __shared__ float rbuf[8][64], sbuf[8][20];
    int tid = threadIdx.x;
    for (int i = tid; i < 2048; i += 256) { int o = i >> 6, d = i & 63; sW1[d * 32 + o] = W1[i]; }
    if (tid < 32) { sb1[tid] = b1[tid]; sW2[tid] = W2[tid]; }
    if (tid < 128) sWo[tid] = Wo[tid];
    if (tid < 64) sfw[tid] = fcoW[tid];
    __syncthreads();
    int w = tid >> 5, l = tid & 31;
    int n = blockIdx.x * 8 + w;
    const float* rn = g_r + (size_t)n * KG * 64;

    for (int k = 0; k < KG; k++) {
        rbuf[w][l] = rn[k * 64 + l]; rbuf[w][l + 32] = rn[k * 64 + l + 32];
        __syncwarp();
        float acc = sb1[l];
        for (int d = 0; d < 64; d++) acc = fmaf(rbuf[w][d], sW1[d * 32 + l], acc);
        float p = tanhe(acc) * sW2[l];
#pragma unroll
        for (int off = 16; off; off >>= 1) p += __shfl_xor_sync(~0u, p, off);
        if (l == 0) sbuf[w][k] = p;
        __syncwarp();
    }
    float sv = (l < KG) ? sbuf[w][l] : -1e30f;
    float mx = sv;
#pragma unroll
    for (int off = 16; off; off >>= 1) mx = fmaxf(mx, __shfl_xor_sync(~0u, mx, off));
    float e = (l < KG) ? __expf(sv - mx) : 0.f;
    float ssum = e;
#pragma unroll
    for (int off = 16; off; off >>= 1) ssum += __shfl_xor_sync(~0u, ssum, off);
    if (l < KG) sbuf[w][l] = __fdividef(e, ssum);
    __syncwarp();

    float a0 = 0.f, a1 = 0.f;
    for (int k = 0; k < KG; k++) {
        float wk = sbuf[w][k];
        a0 = fmaf(wk, rn[k * 64 + l], a0);
        a1 = fmaf(wk, rn[k * 64 + l + 32], a1);
    }
    float rl0 = rn[19 * 64 + l], rl1 = rn[19 * 64 + l + 32];
    float part = rl0 * sWo[l] + rl1 * sWo[l + 32] + a0 * sWo[64 + l] + a1 * sWo[96 + l];
#pragma unroll
    for (int off = 16; off; off >>= 1) part += __shfl_xor_sync(~0u, part, off);
    if (l == 0) out[n] = part + bo[0];

    const float* hf = g_hfc + (size_t)n * KG * 64 + 19 * 64;
    float pp = lrelu(hf[l]) * sfw[l] + lrelu(hf[l + 32]) * sfw[l + 32];
#pragma unroll
    for (int off = 16; off; off >>= 1) pp += __shfl_xor_sync(~0u, pp, off);
    if (l == 0) out[512 + n] = pp + fcob[0];
}

extern "C" void kernel_launch(void* const* d_in, const int* in_sizes, int n_in,
                              void* d_out, int out_size)
{
    const float* x      = (const float*)d_in[0];
    const float* Wih0   = (const float*)d_in[1];
    const float* Whh0   = (const float*)d_in[2];
    const float* bih0   = (const float*)d_in[3];
    const float* bhh0   = (const float*)d_in[4];
    const float* Wih1   = (const float*)d_in[5];
    const float* Whh1   = (const float*)d_in[6];
    const float* bih1   = (const float*)d_in[7];
    const float* bhh1   = (const float*)d_in[8];
    const float* transW = (const float*)d_in[9];
    const float* transb = (const float*)d_in[10];
    const float* avec   = (const float*)d_in[11];
    const float* fcW    = (const float*)d_in[12];
    const float* fcb    = (const float*)d_in[13];
    const float* fcoW   = (const float*)d_in[14];
    const float* fcob   = (const float*)d_in[15];
    const float* inW    = (const float*)d_in[16];
    const float* inb    = (const float*)d_in[17];
    const float* aWih0  = (const float*)d_in[18];
    const float* aWhh0  = (const float*)d_in[19];
    const float* abih0  = (const float*)d_in[20];
    const float* abhh0  = (const float*)d_in[21];
    const float* aWih1  = (const float*)d_in[22];
    const float* aWhh1  = (const float*)d_in[23];
    const float* abih1  = (const float*)d_in[24];
    const float* abhh1  = (const float*)d_in[25];
    const float* att1W  = (const float*)d_in[26];
    const float* att1b  = (const float*)d_in[27];
    const float* att2W  = (const float*)d_in[28];
    const float* outW   = (const float*)d_in[29];
    const float* outb   = (const float*)d_in[30];
    float* out = (float*)d_out;

    void *p_hlast, *p_z, *p_r;
    cudaGetSymbolAddress(&p_hlast, g_hlast);
    cudaGetSymbolAddress(&p_z, g_z);
    cudaGetSymbolAddress(&p_r, g_r);

    constexpr int NTHR = 384;                         // 12 warps, 3/SMSP
    constexpr int SPG = 6, S = (NTHR / 32) * SPG;     // 72 samples/block
    const size_t smemE = (size_t)(1152 + 3 * 12288 + 512 + 2 * S * 64 + S * 64 + 2 * S * 6) * 4;
    const size_t smemA = (size_t)(2 * 24576 + 512 + 512 + 256 + 512 + 2048) * 4;
    const size_t smemAtt = (size_t)(32768 + 512 + 512 + 132 + 8 * 1024) * 4;

    cudaFuncSetAttribute(enc_kernel<SPG, NTHR>,
                         cudaFuncAttributeMaxDynamicSharedMemorySize, (int)smemE);
    cudaFuncSetAttribute(alstm_kernel,
                         cudaFuncAttributeMaxDynamicSharedMemorySize, (int)smemA);
    cudaFuncSetAttribute(att_kernel,
                         cudaFuncAttributeMaxDynamicSharedMemorySize, (int)smemAtt);

    // ---- prep (idempotent; repeated to keep enc_kernel at the profiled
    //      launch slot for ncu visibility) ----
    prep_kernel<<<1, 64>>>(transW, transb, avec);
    prep_kernel<<<1, 64>>>(transW, transb, avec);
    prep_kernel<<<1, 64>>>(transW, transb, avec);

    // ---- encoder: one wave of 143 blocks x 72 samples, 3 warps/SMSP ----
    enc_kernel<SPG, NTHR><<<(NT + S - 1) / S, NTHR, smemE>>>(
        x, Wih0, Whh0, bih0, bhh0, Wih1, Whh1, bih1, bhh1,
        (float*)p_hlast, 60);

    // ---- GAT attention (scores fused in) ----
    att_kernel<<<KG * 4, 256, smemAtt>>>();

    // ---- fc + al_in tanh ----
    fc_kernel<<<80, 256>>>(fcW, fcb, inW, inb);

    // ---- ALSTM: j-split fused 2-layer GRU over K=20, batch 512 ----
    alstm_kernel<<<128, 256, smemA>>>(
        (const float*)p_z, aWih0, aWhh0, abih0, abhh0, aWih1, aWhh1, abih1, abhh1,
        (float*)p_r, 20);

    // ---- head: ALSTM attention + outputs ----
    head_kernel<<<64, 256>>>(att1W, att1b, att2W, outW, outb, fcoW, fcob, out);
}

// round 14
// speedup vs baseline: 1.0560x; 1.0560x over previous
#include <cuda_runtime.h>
#include <cstddef>

#define NT 10240
#define KG 20
#define MG 512

typedef unsigned long long u64;

// ---- scratch (device globals; allocation is forbidden) ----
__device__ float g_hlast[NT * 64];
__device__ float g_hatt[NT * 64];
__device__ float g_hfc[NT * 64];   // layout [m][K][64]
__device__ float g_z[NT * 64];     // layout [m][K][64]
__device__ float g_r[NT * 64];     // layout [m][K][64]
__device__ float g_vec[130];       // v_dst[64] | v_src[64] | c_dst | c_src

// exp-based (accurate) activations — used outside the encoder
__device__ __forceinline__ float sige(float v) {
    return __fdividef(1.f, 1.f + __expf(-v));
}
__device__ __forceinline__ float tanhe(float v) {
    return 1.f - __fdividef(2.f, __expf(2.f * v) + 1.f);
}
// MUFU.TANH-based (encoder only): 1 MUFU op each path
__device__ __forceinline__ float tanha(float v) {
    float r;
    asm("tanh.approx.f32 %0, %1;" : "=f"(r) : "f"(v));
    return r;
}
__device__ __forceinline__ float siga(float v) {
    return fmaf(0.5f, tanha(0.5f * v), 0.5f);
}
__device__ __forceinline__ float lrelu(float v) { return v > 0.f ? v : 0.01f * v; }

__device__ __forceinline__ void fma2(u64& d, u64 a, u64 b) {
    asm("fma.rn.f32x2 %0, %1, %2, %3;" : "=l"(d) : "l"(a), "l"(b), "l"(d));
}
__device__ __forceinline__ u64 pack2(float lo, float hi) {
    u64 r;
    asm("mov.b64 %0, {%1, %2};" : "=l"(r) : "f"(lo), "f"(hi));
    return r;
}
__device__ __forceinline__ float upk(u64 a, float bias) {
    float lo = __uint_as_float((unsigned)(a & 0xffffffffu));
    float hi = __uint_as_float((unsigned)(a >> 32));
    return lo + hi + bias;
}
__device__ __forceinline__ float u64lo(u64 a) { return __uint_as_float((unsigned)(a & 0xffffffffu)); }
__device__ __forceinline__ float u64hi(u64 a) { return __uint_as_float((unsigned)(a >> 32)); }

// ============================================================================
// ENCODER: fused 2-layer GRU, gates fully in registers.
// 256 threads / 8 warps (2/SMSP), SPG=9 samples/warp — FMA-bound config.
// Lane og owns outputs o = j*32+og, j=0..5.
// ============================================================================

template <int SPG, int KDIM, bool ACCRZ>
__device__ __forceinline__ void gemm_pass(const float* __restrict__ inp,
                                          const float* __restrict__ Wp,
                                          u64 (&aRZ)[SPG][4], u64 (&aN)[SPG][2],
                                          int og, int sg)
{
    const u64* W2 = reinterpret_cast<const u64*>(Wp);
    const u64* I2 = reinterpret_cast<const u64*>(inp);
#pragma unroll
    for (int p = 0; p < SPG; p++) {
        if (!ACCRZ) { aRZ[p][0] = 0; aRZ[p][1] = 0; aRZ[p][2] = 0; aRZ[p][3] = 0; }
        aN[p][0] = 0; aN[p][1] = 0;
    }
#pragma unroll 4
    for (int k2 = 0; k2 < KDIM / 2; k2++) {
        u64 w[6];
#pragma unroll
        for (int j = 0; j < 6; j++) w[j] = W2[(k2 * 6 + j) * 32 + og];
#pragma unroll
        for (int p = 0; p < SPG; p++) {
            u64 a = I2[(sg * SPG + p) * (KDIM / 2) + k2];
            fma2(aRZ[p][0], a, w[0]);
            fma2(aRZ[p][1], a, w[1]);
            fma2(aRZ[p][2], a, w[2]);
            fma2(aRZ[p][3], a, w[3]);
            fma2(aN[p][0], a, w[4]);
            fma2(aN[p][1], a, w[5]);
        }
    }
}

template <int SPG>
__device__ __forceinline__ void gemm_dual(const float* __restrict__ inA,
                                          const float* __restrict__ inB,
                                          const float* __restrict__ WA,
                                          const float* __restrict__ WB,
                                          u64 (&aRZ)[SPG][4], u64 (&aNI)[SPG][2],
                                          u64 (&aNH)[SPG][2], int og, int sg)
{
    const u64* WA2 = reinterpret_cast<const u64*>(WA);
    const u64* WB2 = reinterpret_cast<const u64*>(WB);
    const u64* IA2 = reinterpret_cast<const u64*>(inA);
    const u64* IB2 = reinterpret_cast<const u64*>(inB);
#pragma unroll
    for (int p = 0; p < SPG; p++) {
        aRZ[p][0] = 0; aRZ[p][1] = 0; aRZ[p][2] = 0; aRZ[p][3] = 0;
        aNI[p][0] = 0; aNI[p][1] = 0; aNH[p][0] = 0; aNH[p][1] = 0;
    }
#pragma unroll 2
    for (int k2 = 0; k2 < 32; k2++) {
        u64 wa[6], wb[6];
#pragma unroll
        for (int j = 0; j < 6; j++) {
            wa[j] = WA2[(k2 * 6 + j) * 32 + og];
            wb[j] = WB2[(k2 * 6 + j) * 32 + og];
        }
#pragma unroll
        for (int p = 0; p < SPG; p++) {
            u64 a = IA2[(sg * SPG + p) * 32 + k2];
            u64 b = IB2[(sg * SPG + p) * 32 + k2];
            fma2(aRZ[p][0], a, wa[0]); fma2(aRZ[p][0], b, wb[0]);
            fma2(aRZ[p][1], a, wa[1]); fma2(aRZ[p][1], b, wb[1]);
            fma2(aRZ[p][2], a, wa[2]); fma2(aRZ[p][2], b, wb[2]);
            fma2(aRZ[p][3], a, wa[3]); fma2(aRZ[p][3], b, wb[3]);
            fma2(aNI[p][0], a, wa[4]); fma2(aNI[p][1], a, wa[5]);
            fma2(aNH[p][0], b, wb[4]); fma2(aNH[p][1], b, wb[5]);
        }
    }
}

template <int SPG>
__global__ void __launch_bounds__(256, 1)
enc_kernel(const float* __restrict__ x,
           const float* __restrict__ Wih0, const float* __restrict__ Whh0,
           const float* __restrict__ bih0, const float* __restrict__ bhh0,
           const float* __restrict__ Wih1, const float* __restrict__ Whh1,
           const float* __restrict__ bih1, const float* __restrict__ bhh1,
           float* __restrict__ out, int T)
{
    constexpr int S = 8 * SPG;
    extern __shared__ float sm[];
    float* sWih0p = sm;                      // [3*6*64]   K=6 paired
    float* sWhh0p = sWih0p + 1152;           // [32*6*64]  paired
    float* sWih1p = sWhh0p + 12288;
    float* sWhh1p = sWih1p + 12288;
    float* sbrz0  = sWhh1p + 12288;          // [128] bih0+bhh0 (r,z)
    float* sbni0  = sbrz0 + 128;             // [64]
    float* sbnh0  = sbni0 + 64;              // [64]
    float* sbrz1  = sbnh0 + 64;              // [128]
    float* sbni1  = sbrz1 + 128;
    float* sbnh1  = sbni1 + 64;
    float* sh0    = sbnh1 + 64;              // [2][S*64] double buffered
    float* sh1    = sh0 + 2 * S * 64;        // [S*64]
    float* sxt    = sh1 + S * 64;            // [2][S*6]

    const int tid = threadIdx.x;
    const int base = blockIdx.x * S;

    for (int idx = tid; idx < 12288; idx += 256) {
        int og2 = idx & 63;
        int j = (idx >> 6) % 6;
        int k2 = idx / 384;
        int o = j * 32 + (og2 >> 1);
        int k = k2 * 2 + (og2 & 1);
        sWhh0p[idx] = Whh0[o * 64 + k];
        sWih1p[idx] = Wih1[o * 64 + k];
        sWhh1p[idx] = Whh1[o * 64 + k];
    }
    for (int idx = tid; idx < 1152; idx += 256) {
        int og2 = idx & 63;
        int j = (idx >> 6) % 6;
        int k2 = idx / 384;     // < 3
        int o = j * 32 + (og2 >> 1);
        int k = k2 * 2 + (og2 & 1);
        sWih0p[idx] = Wih0[o * 6 + k];
    }
    if (tid < 128) {
        sbrz0[tid] = bih0[tid] + bhh0[tid];
        sbrz1[tid] = bih1[tid] + bhh1[tid];
    } else if (tid < 192) {
        int d = tid - 128;
        sbni0[d] = bih0[128 + d]; sbnh0[d] = bhh0[128 + d];
        sbni1[d] = bih1[128 + d]; sbnh1[d] = bhh1[128 + d];
    }
    for (int idx = tid; idx < 2 * S * 64; idx += 256) sh0[idx] = 0.f;
    for (int idx = tid; idx < S * 64; idx += 256) sh1[idx] = 0.f;
    for (int idx = tid; idx < S * 6; idx += 256) {
        int s = idx / 6, i = idx % 6;
        int gs = base + s;
        sxt[idx] = (gs < NT) ? x[((size_t)gs * T) * 6 + i] : 0.f;
    }
    __syncthreads();

    const int og = tid & 31, sg = tid >> 5;
    constexpr int XN = S * 6;
    constexpr int XR = (XN + 255) / 256;

    u64 aRZ[SPG][4], aNI[SPG][2], aNH[SPG][2];
    float hn0[SPG], hn1[SPG];

    for (int t = 0; t < T; t++) {
        const int cur = t & 1, nxt = cur ^ 1;

        float xr[XR];
        if (t + 1 < T) {
#pragma unroll
            for (int r = 0; r < XR; r++) {
                int idx = tid + r * 256;
                if (idx < XN) {
                    int s = idx / 6, i = idx % 6;
                    int gs = base + s;
                    xr[r] = (gs < NT) ? x[((size_t)gs * T + t + 1) * 6 + i] : 0.f;
                }
            }
        }

        // -------- layer 0 --------
        gemm_pass<SPG, 6, false>(sxt + cur * XN, sWih0p, aRZ, aNI, og, sg);
        gemm_pass<SPG, 64, true>(sh0 + cur * S * 64, sWhh0p, aRZ, aNH, og, sg);
#pragma unroll
        for (int p = 0; p < SPG; p++) {
            int s = sg * SPG + p;
            float r0 = siga(upk(aRZ[p][0], sbrz0[og]));
            float r1 = siga(upk(aRZ[p][1], sbrz0[32 + og]));
            float z0 = siga(upk(aRZ[p][2], sbrz0[64 + og]));
            float z1 = siga(upk(aRZ[p][3], sbrz0[96 + og]));
            float n0 = tanha(upk(aNI[p][0], sbni0[og]) + r0 * upk(aNH[p][0], sbnh0[og]));
            float n1 = tanha(upk(aNI[p][1], sbni0[32 + og]) + r1 * upk(aNH[p][1], sbnh0[32 + og]));
            float hp0 = sh0[cur * S * 64 + s * 64 + og];
            float hp1 = sh0[cur * S * 64 + s * 64 + 32 + og];
            hn0[p] = n0 + z0 * (hp0 - n0);
            hn1[p] = n1 + z1 * (hp1 - n1);
        }
#pragma unroll
        for (int p = 0; p < SPG; p++) {
            int s = sg * SPG + p;
            sh0[nxt * S * 64 + s * 64 + og] = hn0[p];
            sh0[nxt * S * 64 + s * 64 + 32 + og] = hn1[p];
        }
        if (t + 1 < T) {
#pragma unroll
            for (int r = 0; r < XR; r++) {
                int idx = tid + r * 256;
                if (idx < XN) sxt[nxt * XN + idx] = xr[r];
            }
        }
        __syncthreads();   // B1

        // -------- layer 1: fused dual GEMM + EW --------
        gemm_dual<SPG>(sh0 + nxt * S * 64, sh1, sWih1p, sWhh1p, aRZ, aNI, aNH, og, sg);
#pragma unroll
        for (int p = 0; p < SPG; p++) {
            int s = sg * SPG + p;
            float r0 = siga(upk(aRZ[p][0], sbrz1[og]));
            float r1 = siga(upk(aRZ[p][1], sbrz1[32 + og]));
            float z0 = siga(upk(aRZ[p][2], sbrz1[64 + og]));
            float z1 = siga(upk(aRZ[p][3], sbrz1[96 + og]));
            float n0 = tanha(upk(aNI[p][0], sbni1[og]) + r0 * upk(aNH[p][0], sbnh1[og]));
            float n1 = tanha(upk(aNI[p][1], sbni1[32 + og]) + r1 * upk(aNH[p][1], sbnh1[32 + og]));
            float hp0 = sh1[s * 64 + og];
            float hp1 = sh1[s * 64 + 32 + og];
            hn0[p] = n0 + z0 * (hp0 - n0);
            hn1[p] = n1 + z1 * (hp1 - n1);
        }
        if (t == T - 1) {
#pragma unroll
            for (int p = 0; p < SPG; p++) {
                int gs = base + sg * SPG + p;
                if (gs < NT) {
                    out[(size_t)gs * 64 + og] = hn0[p];
                    out[(size_t)gs * 64 + 32 + og] = hn1[p];
                }
            }
        }
        __syncthreads();   // B2
#pragma unroll
        for (int p = 0; p < SPG; p++) {
            int s = sg * SPG + p;
            sh1[s * 64 + og] = hn0[p];
            sh1[s * 64 + 32 + og] = hn1[p];
        }
    }
}

// ============================================================================
// ALSTM: j-split 2-layer GRU (unchanged; exp-based activations).
// ============================================================================
__global__ void __launch_bounds__(256, 1)
alstm_kernel(const float* __restrict__ zin,
             const float* __restrict__ Wih0, const float* __restrict__ Whh0,
             const float* __restrict__ bih0, const float* __restrict__ bhh0,
             const float* __restrict__ Wih1, const float* __restrict__ Whh1,
             const float* __restrict__ bih1, const float* __restrict__ bhh1,
             float* __restrict__ outr, int T)
{
    extern __shared__ float sm[];
    float* sW0   = sm;                 // [24576]
    float* sW1   = sW0 + 24576;        // [24576]
    float* sbrz0 = sW1 + 24576;        // [128]
    float* sbni0 = sbrz0 + 128;        // [64]
    float* sbnh0 = sbni0 + 64;
    float* sbrz1 = sbnh0 + 64;         // [128]
    float* sbni1 = sbrz1 + 128;
    float* sbnh1 = sbni1 + 64;         // biases end at +512
    float* sh0   = sbnh1 + 64;         // [2][256]
    float* sh1   = sh0 + 512;          // [256]
    float* sxt   = sh1 + 256;          // [2][256]
    float* sgA   = sxt + 512;          // [4][256]  layer0 gates
    float* sgB   = sgA + 1024;         // [4][256]  layer1 gates

    const int tid = threadIdx.x;
    const int base = blockIdx.x * 4;

    for (int idx = tid; idx < 24576; idx += 256) {
        int og2 = idx & 63;
        int col = idx >> 6;            // k2*12 + j*2 + src
        int src = col & 1;
        int j = (col >> 1) % 6;
        int k2 = col / 12;
        int o = j * 32 + (og2 >> 1);
        int k = k2 * 2 + (og2 & 1);
        sW0[idx] = src ? Whh0[o * 64 + k] : Wih0[o * 64 + k];
        sW1[idx] = src ? Whh1[o * 64 + k] : Wih1[o * 64 + k];
    }
    if (tid < 128) {
        sbrz0[tid] = bih0[tid] + bhh0[tid];
        sbrz1[tid] = bih1[tid] + bhh1[tid];
    } else if (tid < 192) {
        int d = tid - 128;
        sbni0[d] = bih0[128 + d]; sbnh0[d] = bhh0[128 + d];
        sbni1[d] = bih1[128 + d]; sbnh1[d] = bhh1[128 + d];
    }
    for (int idx = tid; idx < 512; idx += 256) sh0[idx] = 0.f;
    sh1[tid] = 0.f;
    {
        int s = tid >> 6, d = tid & 63;
        sxt[tid] = zin[((size_t)(base + s) * T) * 64 + d];
    }
    __syncthreads();

    const int og = tid & 31;
    const int w = tid >> 5;

    const u64* W02 = reinterpret_cast<const u64*>(sW0);
    const u64* W12 = reinterpret_cast<const u64*>(sW1);

    for (int t = 0; t < T; t++) {
        const int cur = t & 1, nxt = cur ^ 1;

        float xpre = 0.f;
        if (t + 1 < T) {
            int s = tid >> 6, d = tid & 63;
            xpre = zin[((size_t)(base + s) * T + t + 1) * 64 + d];
        }

        // ---- layer 0 GEMM (warps 0-5) ----
        if (w < 6) {
            const u64* X2 = reinterpret_cast<const u64*>(sxt + cur * 256);
            const u64* H2 = reinterpret_cast<const u64*>(sh0 + cur * 256);
            u64 aI[4] = {0, 0, 0, 0}, aH[4] = {0, 0, 0, 0};
#pragma unroll 4
            for (int k2 = 0; k2 < 32; k2++) {
                u64 wI = W02[(k2 * 12 + w * 2) * 32 + og];
                u64 wH = W02[(k2 * 12 + w * 2 + 1) * 32 + og];
#pragma unroll
                for (int s = 0; s < 4; s++) {
                    fma2(aI[s], X2[s * 32 + k2], wI);
                    fma2(aH[s], H2[s * 32 + k2], wH);
                }
            }
#pragma unroll
            for (int s = 0; s < 4; s++) {
                if (w < 4) {
                    sgA[s * 256 + w * 32 + og] = upk(aI[s], 0.f) + upk(aH[s], sbrz0[w * 32 + og]);
                } else {
                    sgA[s * 256 + 128 + (w - 4) * 32 + og] = upk(aI[s], sbni0[(w - 4) * 32 + og]);
                    sgA[s * 256 + 192 + (w - 4) * 32 + og] = upk(aH[s], sbnh0[(w - 4) * 32 + og]);
                }
            }
        }
        if (t + 1 < T) sxt[nxt * 256 + tid] = xpre;
        __syncthreads();   // B1

        // ---- layer 0 EW (warps 0-3, warp = sample) ----
        if (w < 4) {
            const float* g = sgA + w * 256;
            float r0 = sige(g[og]),       r1 = sige(g[32 + og]);
            float z0 = sige(g[64 + og]),  z1 = sige(g[96 + og]);
            float n0 = tanhe(g[128 + og] + r0 * g[192 + og]);
            float n1 = tanhe(g[160 + og] + r1 * g[224 + og]);
            float hp0 = sh0[cur * 256 + w * 64 + og];
            float hp1 = sh0[cur * 256 + w * 64 + 32 + og];
            sh0[nxt * 256 + w * 64 + og]      = n0 + z0 * (hp0 - n0);
            sh0[nxt * 256 + w * 64 + 32 + og] = n1 + z1 * (hp1 - n1);
        }
        __syncthreads();   // B2

        // ---- layer 1 GEMM (warps 0-5) ----
        if (w < 6) {
            const u64* X2 = reinterpret_cast<const u64*>(sh0 + nxt * 256);
            const u64* H2 = reinterpret_cast<const u64*>(sh1);
            u64 aI[4] = {0, 0, 0, 0}, aH[4] = {0, 0, 0, 0};
#pragma unroll 4
            for (int k2 = 0; k2 < 32; k2++) {
                u64 wI = W12[(k2 * 12 + w * 2) * 32 + og];
                u64 wH = W12[(k2 * 12 + w * 2 + 1) * 32 + og];
#pragma unroll
                for (int s = 0; s < 4; s++) {
                    fma2(aI[s], X2[s * 32 + k2], wI);
                    fma2(aH[s], H2[s * 32 + k2], wH);
                }
            }
#pragma unroll
            for (int s = 0; s < 4; s++) {
                if (w < 4) {
                    sgB[s * 256 + w * 32 + og] = upk(aI[s], 0.f) + upk(aH[s], sbrz1[w * 32 + og]);
                } else {
                    sgB[s * 256 + 128 + (w - 4) * 32 + og] = upk(aI[s], sbni1[(w - 4) * 32 + og]);
                    sgB[s * 256 + 192 + (w - 4) * 32 + og] = upk(aH[s], sbnh1[(w - 4) * 32 + og]);
                }
            }
        }
        __syncthreads();   // B3

        // ---- layer 1 EW + output (warps 0-3) ----
        if (w < 4) {
            const float* g = sgB + w * 256;
            float r0 = sige(g[og]),       r1 = sige(g[32 + og]);
            float z0 = sige(g[64 + og]),  z1 = sige(g[96 + og]);
            float n0 = tanhe(g[128 + og] + r0 * g[192 + og]);
            float n1 = tanhe(g[160 + og] + r1 * g[224 + og]);
            float hp0 = sh1[w * 64 + og];
            float hp1 = sh1[w * 64 + 32 + og];
            float h0n = n0 + z0 * (hp0 - n0);
            float h1n = n1 + z1 * (hp1 - n1);
            outr[((size_t)(base + w) * T + t) * 64 + og]      = h0n;
            outr[((size_t)(base + w) * T + t) * 64 + 32 + og] = h1n;
            sh1[w * 64 + og] = h0n;
            sh1[w * 64 + 32 + og] = h1n;
        }
        // safe: next readers of sh1 (layer-1 GEMM of t+1) sit behind B1+B2
    }
}

// v_dst = trans_W^T a[:64], v_src = trans_W^T a[64:], plus bias dots.
__global__ void prep_kernel(const float* __restrict__ tW, const float* __restrict__ tb,
                            const float* __restrict__ a)
{
    int d = threadIdx.x;  // 64 threads
    float vd = 0.f, vs = 0.f;
    for (int o = 0; o < 64; o++) {
        vd = fmaf(tW[o * 64 + d], a[o], vd);
        vs = fmaf(tW[o * 64 + d], a[64 + o], vs);
    }
    g_vec[d] = vd; g_vec[64 + d] = vs;
    if (d == 0) {
        float cd = 0.f, cs = 0.f;
        for (int o = 0; o < 64; o++) { cd = fmaf(tb[o], a[o], cd); cs = fmaf(tb[o], a[64 + o], cs); }
        g_vec[128] = cd; g_vec[129] = cs;
    }
}

// Dense GAT: per-node scores (fused) + attention + aggregate + residual.
// grid = KG*4 (group x 128-row chunk). R5 inner loop; ew buffer 1024/warp.
__global__ void att_kernel()
{
    extern __shared__ float sm[];
    float* sh  = sm;                 // [512*64] plain rows
    float* sd  = sm + 32768;         // [512] s_dst
    float* ssc = sd + 512;           // [512] s_src
    float* sv  = ssc + 512;          // [132]
    float* se  = sv + 132;           // [8 warps][8 rows][128] exp rows
    int k = blockIdx.x >> 2, chunk = blockIdx.x & 3;
    int tid = threadIdx.x, l = tid & 31, w = tid >> 5;
    const float* hg = g_hlast + (size_t)k * 512 * 64;
    for (int i = tid; i < 32768; i += 256) sh[i] = hg[i];
    if (tid < 130) sv[tid] = g_vec[tid];
    __syncthreads();

    // scores for all 512 nodes: warp w owns nodes [w*64, w*64+64)
    for (int i = 0; i < 64; i++) {
        int n = w * 64 + i;
        float h0 = sh[n * 64 + l], h1 = sh[n * 64 + 32 + l];
        float ps = h0 * sv[64 + l] + h1 * sv[96 + l];
        float pd = h0 * sv[l] + h1 * sv[32 + l];
#pragma unroll
        for (int off = 16; off; off >>= 1) {
            ps += __shfl_xor_sync(~0u, ps, off);
            pd += __shfl_xor_sync(~0u, pd, off);
        }
        if (l == 0) { ssc[n] = ps + sv[129]; sd[n] = pd + sv[128]; }
    }
    __syncthreads();

    // group max of s_dst (lrelu monotone -> row max = lrelu(s_src_i + dmax))
    float dm = -1e30f;
    for (int i = l; i < 512; i += 32) dm = fmaxf(dm, sd[i]);
#pragma unroll
    for (int off = 16; off; off >>= 1) dm = fmaxf(dm, __shfl_xor_sync(~0u, dm, off));

    const u64* sh2 = reinterpret_cast<const u64*>(sh);
    float* ew = se + w * 1024;

    for (int batch = 0; batch < 2; batch++) {
        int b0 = chunk * 128 + w * 16 + batch * 8;
        float si[8], mi[8], den[8];
        u64 acc[8];
#pragma unroll
        for (int i = 0; i < 8; i++) {
            si[i] = ssc[b0 + i];
            mi[i] = lrelu(si[i] + dm);
            den[i] = 0.f; acc[i] = 0ull;
        }
        for (int jt = 0; jt < 4; jt++) {
#pragma unroll
            for (int i = 0; i < 8; i++) {
#pragma unroll
                for (int q = 0; q < 4; q++) {
                    int j = jt * 128 + q * 32 + l;
                    float e = __expf(lrelu(si[i] + sd[j]) - mi[i]);
                    ew[i * 128 + q * 32 + l] = e;
                    den[i] += e;
                }
            }
            __syncwarp();
#pragma unroll 4
            for (int j0 = 0; j0 < 128; j0++) {
                int j = jt * 128 + j0;
                u64 hv = sh2[j * 32 + l];
#pragma unroll
                for (int i = 0; i < 8; i++) {
                    u64 e2 = (u64)__float_as_uint(ew[i * 128 + j0]);
                    e2 |= e2 << 32;
                    fma2(acc[i], e2, hv);
                }
            }
            __syncwarp();
        }
#pragma unroll
        for (int i = 0; i < 8; i++) {
            float d = den[i];
#pragma unroll
            for (int off = 16; off; off >>= 1) d += __shfl_xor_sync(~0u, d, off);
            float inv = __fdividef(1.f, d);
            int r = b0 + i;
            float* o = g_hatt + ((size_t)k * 512 + r) * 64;
            o[2 * l]     = fmaf(u64lo(acc[i]), inv, sh[r * 64 + 2 * l]);
            o[2 * l + 1] = fmaf(u64hi(acc[i]), inv, sh[r * 64 + 2 * l + 1]);
        }
    }
}

// hfc = hatt @ fc_W^T + fc_b ([m][K][64] layout); z = tanh(hfc @ al_in_W^T + al_in_b).
__global__ void fc_kernel(const float* __restrict__ fcW, const float* __restrict__ fcb,
                          const float* __restrict__ inW, const float* __restrict__ inb)
{
    __shared__ float sWf[64 * 64], sWi[64 * 64], sbf[64], sbi[64];
    __shared__ u64 sr2[8][64], sf2[8][64];
    int tid = threadIdx.x;
    for (int i = tid; i < 4096; i += 256) {
        int o = i >> 6, d = i & 63;
        sWf[d * 64 + o] = fcW[i];
        sWi[d * 64 + o] = inW[i];
    }
    if (tid < 64) { sbf[tid] = fcb[tid]; sbi[tid] = inb[tid]; }
    __syncthreads();
    const u64* sWf2 = reinterpret_cast<const u64*>(sWf);
    const u64* sWi2 = reinterpret_cast<const u64*>(sWi);
    int w = tid >> 5, l = tid & 31;
    for (int it = 0; it < 16; it++) {
        int n = blockIdx.x * 128 + it * 8 + w;  // 80*128 = 10240
        const float* hr = g_hatt + (size_t)n * 64;
        float v0 = hr[l], v1 = hr[l + 32];
        sr2[w][l] = pack2(v0, v0); sr2[w][l + 32] = pack2(v1, v1);
        __syncwarp();
        u64 acc = 0ull;
#pragma unroll 4
        for (int d = 0; d < 64; d++)
            fma2(acc, sr2[w][d], sWf2[d * 32 + l]);
        float a0 = u64lo(acc) + sbf[2 * l];
        float a1 = u64hi(acc) + sbf[2 * l + 1];
        int kk = n >> 9, ii = n & 511;
        float* of = g_hfc + ((size_t)ii * KG + kk) * 64;
        *reinterpret_cast<u64*>(&of[2 * l]) = pack2(a0, a1);
        sf2[w][2 * l] = pack2(a0, a0); sf2[w][2 * l + 1] = pack2(a1, a1);
        __syncwarp();
        u64 acc2 = 0ull;
#pragma unroll 4
        for (int d = 0; d < 64; d++)
            fma2(acc2, sf2[w][d], sWi2[d * 32 + l]);
        float z0 = tanhe(u64lo(acc2) + sbi[2 * l]);
        float z1 = tanhe(u64hi(acc2) + sbi[2 * l + 1]);
        float* oz = g_z + ((size_t)ii * KG + kk) * 64;
        *reinterpret_cast<u64*>(&oz[2 * l]) = pack2(z0, z1);
        __syncwarp();
    }
}

// ALSTM attention head + final outputs. Warp per sample. grid = 64.
__global__ void head_kernel(const float* __restrict__ W1, const float* __restrict__ b1,
                            const float* __restrict__ W2,
                            const float* __restrict__ Wo, const float* __restrict__ bo,
                            const float* __restrict__ fcoW, const float* __restrict__ fcob,
                            float* __restrict__ out)
{
    __shared__ float sW1[64 * 32], sb1[32], sW2[32], sWo[128], sfw[64];
    __shared__ float rbuf[8][64], sbuf[8][20];
    int tid = threadIdx.x;
    for (int i = tid; i < 2048; i += 256) { int o = i >> 6, d = i & 63; sW1[d * 32 + o] = W1[i]; }
    if (tid < 32) { sb1[tid] = b1[tid]; sW2[tid] = W2[tid]; }
    if (tid < 128) sWo[tid] = Wo[tid];
    if (tid < 64) sfw[tid] = fcoW[tid];
    __syncthreads();
    int w = tid >> 5, l = tid & 31;
    int n = blockIdx.x * 8 + w;
    const float* rn = g_r + (size_t)n * KG * 64;

    for (int k = 0; k < KG; k++) {
        rbuf[w][l] = rn[k * 64 + l]; rbuf[w][l + 32] = rn[k * 64 + l + 32];
        __syncwarp();
        float acc = sb1[l];
        for (int d = 0; d < 64; d++) acc = fmaf(rbuf[w][d], sW1[d * 32 + l], acc);
        float p = tanhe(acc) * sW2[l];
#pragma unroll
        for (int off = 16; off; off >>= 1) p += __shfl_xor_sync(~0u, p, off);
        if (l == 0) sbuf[w][k] = p;
        __syncwarp();
    }
    float sv = (l < KG) ? sbuf[w][l] : -1e30f;
    float mx = sv;
#pragma unroll
    for (int off = 16; off; off >>= 1) mx = fmaxf(mx, __shfl_xor_sync(~0u, mx, off));
    float e = (l < KG) ? __expf(sv - mx) : 0.f;
    float ssum = e;
#pragma unroll
    for (int off = 16; off; off >>= 1) ssum += __shfl_xor_sync(~0u, ssum, off);
    if (l < KG) sbuf[w][l] = __fdividef(e, ssum);
    __syncwarp();

    float a0 = 0.f, a1 = 0.f;
    for (int k = 0; k < KG; k++) {
        float wk = sbuf[w][k];
        a0 = fmaf(wk, rn[k * 64 + l], a0);
        a1 = fmaf(wk, rn[k * 64 + l + 32], a1);
    }
    float rl0 = rn[19 * 64 + l], rl1 = rn[19 * 64 + l + 32];
    float part = rl0 * sWo[l] + rl1 * sWo[l + 32] + a0 * sWo[64 + l] + a1 * sWo[96 + l];
#pragma unroll
    for (int off = 16; off; off >>= 1) part += __shfl_xor_sync(~0u, part, off);
    if (l == 0) out[n] = part + bo[0];

    const float* hf = g_hfc + (size_t)n * KG * 64 + 19 * 64;
    float pp = lrelu(hf[l]) * sfw[l] + lrelu(hf[l + 32]) * sfw[l + 32];
#pragma unroll
    for (int off = 16; off; off >>= 1) pp += __shfl_xor_sync(~0u, pp, off);
    if (l == 0) out[512 + n] = pp + fcob[0];
}

extern "C" void kernel_launch(void* const* d_in, const int* in_sizes, int n_in,
                              void* d_out, int out_size)
{
    const float* x      = (const float*)d_in[0];
    const float* Wih0   = (const float*)d_in[1];
    const float* Whh0   = (const float*)d_in[2];
    const float* bih0   = (const float*)d_in[3];
    const float* bhh0   = (const float*)d_in[4];
    const float* Wih1   = (const float*)d_in[5];
    const float* Whh1   = (const float*)d_in[6];
    const float* bih1   = (const float*)d_in[7];
    const float* bhh1   = (const float*)d_in[8];
    const float* transW = (const float*)d_in[9];
    const float* transb = (const float*)d_in[10];
    const float* avec   = (const float*)d_in[11];
    const float* fcW    = (const float*)d_in[12];
    const float* fcb    = (const float*)d_in[13];
    const float* fcoW   = (const float*)d_in[14];
    const float* fcob   = (const float*)d_in[15];
    const float* inW    = (const float*)d_in[16];
    const float* inb    = (const float*)d_in[17];
    const float* aWih0  = (const float*)d_in[18];
    const float* aWhh0  = (const float*)d_in[19];
    const float* abih0  = (const float*)d_in[20];
    const float* abhh0  = (const float*)d_in[21];
    const float* aWih1  = (const float*)d_in[22];
    const float* aWhh1  = (const float*)d_in[23];
    const float* abih1  = (const float*)d_in[24];
    const float* abhh1  = (const float*)d_in[25];
    const float* att1W  = (const float*)d_in[26];
    const float* att1b  = (const float*)d_in[27];
    const float* att2W  = (const float*)d_in[28];
    const float* outW   = (const float*)d_in[29];
    const float* outb   = (const float*)d_in[30];
    float* out = (float*)d_out;

    void *p_hlast, *p_z, *p_r;
    cudaGetSymbolAddress(&p_hlast, g_hlast);
    cudaGetSymbolAddress(&p_z, g_z);
    cudaGetSymbolAddress(&p_r, g_r);

    constexpr int SPG = 9, S = 8 * SPG;               // 72 samples/block, 256 thr
    const size_t smemE = (size_t)(1152 + 3 * 12288 + 512 + 2 * S * 64 + S * 64 + 2 * S * 6) * 4;
    const size_t smemA = (size_t)(2 * 24576 + 512 + 512 + 256 + 512 + 2048) * 4;
    const size_t smemAtt = (size_t)(32768 + 512 + 512 + 132 + 8 * 1024) * 4;

    cudaFuncSetAttribute(enc_kernel<SPG>,
                         cudaFuncAttributeMaxDynamicSharedMemorySize, (int)smemE);
    cudaFuncSetAttribute(alstm_kernel,
                         cudaFuncAttributeMaxDynamicSharedMemorySize, (int)smemA);
    cudaFuncSetAttribute(att_kernel,
                         cudaFuncAttributeMaxDynamicSharedMemorySize, (int)smemAtt);

    // ---- prep (idempotent; repeated to keep enc_kernel at the profiled
    //      launch slot for ncu visibility) ----
    prep_kernel<<<1, 64>>>(transW, transb, avec);
    prep_kernel<<<1, 64>>>(transW, transb, avec);
    prep_kernel<<<1, 64>>>(transW, transb, avec);

    // ---- encoder: one wave of 143 blocks x 72 samples, 256 threads ----
    enc_kernel<SPG><<<(NT + S - 1) / S, 256, smemE>>>(
        x, Wih0, Whh0, bih0, bhh0, Wih1, Whh1, bih1, bhh1,
        (float*)p_hlast, 60);

    // ---- GAT attention (scores fused in) ----
    att_kernel<<<KG * 4, 256, smemAtt>>>();

    // ---- fc + al_in tanh ----
    fc_kernel<<<80, 256>>>(fcW, fcb, inW, inb);

    // ---- ALSTM: j-split fused 2-layer GRU over K=20, batch 512 ----
    alstm_kernel<<<128, 256, smemA>>>(
        (const float*)p_z, aWih0, aWhh0, abih0, abhh0, aWih1, aWhh1, abih1, abhh1,
        (float*)p_r, 20);

    // ---- head: ALSTM attention + outputs ----
    head_kernel<<<64, 256>>>(att1W, att1b, att2W, outW, outb, fcoW, fcob, out);
}

// round 15
// speedup vs baseline: 1.0955x; 1.0374x over previous
#include <cuda_runtime.h>
#include <cstddef>

#define NT 10240
#define KG 20
#define MG 512

typedef unsigned long long u64;

// ---- scratch (device globals; allocation is forbidden) ----
__device__ float g_hlast[NT * 64];
__device__ float g_hatt[NT * 64];
__device__ float g_hfc[NT * 64];   // layout [m][K][64]
__device__ float g_z[NT * 64];     // layout [m][K][64]
__device__ float g_r[NT * 64];     // layout [m][K][64]
__device__ float g_vec[130];       // v_dst[64] | v_src[64] | c_dst | c_src

// exp-based (accurate) activations — used outside the encoder
__device__ __forceinline__ float sige(float v) {
    return __fdividef(1.f, 1.f + __expf(-v));
}
__device__ __forceinline__ float tanhe(float v) {
    return 1.f - __fdividef(2.f, __expf(2.f * v) + 1.f);
}
// MUFU.TANH-based (encoder only): 1 MUFU op each path
__device__ __forceinline__ float tanha(float v) {
    float r;
    asm("tanh.approx.f32 %0, %1;" : "=f"(r) : "f"(v));
    return r;
}
__device__ __forceinline__ float siga(float v) {
    return fmaf(0.5f, tanha(0.5f * v), 0.5f);
}
__device__ __forceinline__ float lrelu(float v) { return v > 0.f ? v : 0.01f * v; }

__device__ __forceinline__ void fma2(u64& d, u64 a, u64 b) {
    asm("fma.rn.f32x2 %0, %1, %2, %3;" : "=l"(d) : "l"(a), "l"(b), "l"(d));
}
__device__ __forceinline__ u64 pack2(float lo, float hi) {
    u64 r;
    asm("mov.b64 %0, {%1, %2};" : "=l"(r) : "f"(lo), "f"(hi));
    return r;
}
__device__ __forceinline__ float upk(u64 a, float bias) {
    float lo = __uint_as_float((unsigned)(a & 0xffffffffu));
    float hi = __uint_as_float((unsigned)(a >> 32));
    return lo + hi + bias;
}
__device__ __forceinline__ float u64lo(u64 a) { return __uint_as_float((unsigned)(a & 0xffffffffu)); }
__device__ __forceinline__ float u64hi(u64 a) { return __uint_as_float((unsigned)(a >> 32)); }

// ============================================================================
// ENCODER: fused 2-layer GRU, gates fully in registers.
// 256 threads / 8 warps (2/SMSP), SPG=9 samples/warp.
// KEY: warps are fully independent after weight load (each warp owns its 9
// samples end-to-end), so per-step sync is __syncwarp only — warps dephase,
// overlapping one warp's MUFU-EW with the other's FMA-GEMM on each SMSP.
// ============================================================================

template <int SPG, int KDIM, bool ACCRZ>
__device__ __forceinline__ void gemm_pass(const float* __restrict__ inp,
                                          const float* __restrict__ Wp,
                                          u64 (&aRZ)[SPG][4], u64 (&aN)[SPG][2],
                                          int og, int sg)
{
    const u64* W2 = reinterpret_cast<const u64*>(Wp);
    const u64* I2 = reinterpret_cast<const u64*>(inp);
#pragma unroll
    for (int p = 0; p < SPG; p++) {
        if (!ACCRZ) { aRZ[p][0] = 0; aRZ[p][1] = 0; aRZ[p][2] = 0; aRZ[p][3] = 0; }
        aN[p][0] = 0; aN[p][1] = 0;
    }
#pragma unroll 4
    for (int k2 = 0; k2 < KDIM / 2; k2++) {
        u64 w[6];
#pragma unroll
        for (int j = 0; j < 6; j++) w[j] = W2[(k2 * 6 + j) * 32 + og];
#pragma unroll
        for (int p = 0; p < SPG; p++) {
            u64 a = I2[(sg * SPG + p) * (KDIM / 2) + k2];
            fma2(aRZ[p][0], a, w[0]);
            fma2(aRZ[p][1], a, w[1]);
            fma2(aRZ[p][2], a, w[2]);
            fma2(aRZ[p][3], a, w[3]);
            fma2(aN[p][0], a, w[4]);
            fma2(aN[p][1], a, w[5]);
        }
    }
}

template <int SPG>
__device__ __forceinline__ void gemm_dual(const float* __restrict__ inA,
                                          const float* __restrict__ inB,
                                          const float* __restrict__ WA,
                                          const float* __restrict__ WB,
                                          u64 (&aRZ)[SPG][4], u64 (&aNI)[SPG][2],
                                          u64 (&aNH)[SPG][2], int og, int sg)
{
    const u64* WA2 = reinterpret_cast<const u64*>(WA);
    const u64* WB2 = reinterpret_cast<const u64*>(WB);
    const u64* IA2 = reinterpret_cast<const u64*>(inA);
    const u64* IB2 = reinterpret_cast<const u64*>(inB);
#pragma unroll
    for (int p = 0; p < SPG; p++) {
        aRZ[p][0] = 0; aRZ[p][1] = 0; aRZ[p][2] = 0; aRZ[p][3] = 0;
        aNI[p][0] = 0; aNI[p][1] = 0; aNH[p][0] = 0; aNH[p][1] = 0;
    }
#pragma unroll 2
    for (int k2 = 0; k2 < 32; k2++) {
        u64 wa[6], wb[6];
#pragma unroll
        for (int j = 0; j < 6; j++) {
            wa[j] = WA2[(k2 * 6 + j) * 32 + og];
            wb[j] = WB2[(k2 * 6 + j) * 32 + og];
        }
#pragma unroll
        for (int p = 0; p < SPG; p++) {
            u64 a = IA2[(sg * SPG + p) * 32 + k2];
            u64 b = IB2[(sg * SPG + p) * 32 + k2];
            fma2(aRZ[p][0], a, wa[0]); fma2(aRZ[p][0], b, wb[0]);
            fma2(aRZ[p][1], a, wa[1]); fma2(aRZ[p][1], b, wb[1]);
            fma2(aRZ[p][2], a, wa[2]); fma2(aRZ[p][2], b, wb[2]);
            fma2(aRZ[p][3], a, wa[3]); fma2(aRZ[p][3], b, wb[3]);
            fma2(aNI[p][0], a, wa[4]); fma2(aNI[p][1], a, wa[5]);
            fma2(aNH[p][0], b, wb[4]); fma2(aNH[p][1], b, wb[5]);
        }
    }
}

template <int SPG>
__global__ void __launch_bounds__(256, 1)
enc_kernel(const float* __restrict__ x,
           const float* __restrict__ Wih0, const float* __restrict__ Whh0,
           const float* __restrict__ bih0, const float* __restrict__ bhh0,
           const float* __restrict__ Wih1, const float* __restrict__ Whh1,
           const float* __restrict__ bih1, const float* __restrict__ bhh1,
           float* __restrict__ out, int T)
{
    constexpr int S = 8 * SPG;
    extern __shared__ float sm[];
    float* sWih0p = sm;                      // [3*6*64]   K=6 paired
    float* sWhh0p = sWih0p + 1152;           // [32*6*64]  paired
    float* sWih1p = sWhh0p + 12288;
    float* sWhh1p = sWih1p + 12288;
    float* sbrz0  = sWhh1p + 12288;          // [128] bih0+bhh0 (r,z)
    float* sbni0  = sbrz0 + 128;             // [64]
    float* sbnh0  = sbni0 + 64;              // [64]
    float* sbrz1  = sbnh0 + 64;              // [128]
    float* sbni1  = sbrz1 + 128;
    float* sbnh1  = sbni1 + 64;
    float* sh0    = sbnh1 + 64;              // [2][S*64] double buffered
    float* sh1    = sh0 + 2 * S * 64;        // [S*64]
    float* sxt    = sh1 + S * 64;            // [2][S*6]

    const int tid = threadIdx.x;
    const int base = blockIdx.x * S;

    for (int idx = tid; idx < 12288; idx += 256) {
        int og2 = idx & 63;
        int j = (idx >> 6) % 6;
        int k2 = idx / 384;
        int o = j * 32 + (og2 >> 1);
        int k = k2 * 2 + (og2 & 1);
        sWhh0p[idx] = Whh0[o * 64 + k];
        sWih1p[idx] = Wih1[o * 64 + k];
        sWhh1p[idx] = Whh1[o * 64 + k];
    }
    for (int idx = tid; idx < 1152; idx += 256) {
        int og2 = idx & 63;
        int j = (idx >> 6) % 6;
        int k2 = idx / 384;     // < 3
        int o = j * 32 + (og2 >> 1);
        int k = k2 * 2 + (og2 & 1);
        sWih0p[idx] = Wih0[o * 6 + k];
    }
    if (tid < 128) {
        sbrz0[tid] = bih0[tid] + bhh0[tid];
        sbrz1[tid] = bih1[tid] + bhh1[tid];
    } else if (tid < 192) {
        int d = tid - 128;
        sbni0[d] = bih0[128 + d]; sbnh0[d] = bhh0[128 + d];
        sbni1[d] = bih1[128 + d]; sbnh1[d] = bhh1[128 + d];
    }
    for (int idx = tid; idx < 2 * S * 64; idx += 256) sh0[idx] = 0.f;
    for (int idx = tid; idx < S * 64; idx += 256) sh1[idx] = 0.f;
    for (int idx = tid; idx < S * 6; idx += 256) {
        int s = idx / 6, i = idx % 6;
        int gs = base + s;
        sxt[idx] = (gs < NT) ? x[((size_t)gs * T) * 6 + i] : 0.f;
    }
    __syncthreads();   // ONE barrier: weights/biases/initial state visible

    const int og = tid & 31, sg = tid >> 5;
    constexpr int XN = S * 6;
    constexpr int WX = SPG * 6;              // x floats per warp per step (54)
    constexpr int WXR = (WX + 31) / 32;      // rounds per lane (2)

    u64 aRZ[SPG][4], aNI[SPG][2], aNH[SPG][2];
    float hn0[SPG], hn1[SPG];

    for (int t = 0; t < T; t++) {
        const int cur = t & 1, nxt = cur ^ 1;

        // per-warp x(t+1) prefetch (own samples only — no cross-warp traffic)
        float xr[WXR];
        if (t + 1 < T) {
#pragma unroll
            for (int r = 0; r < WXR; r++) {
                int idx = og + r * 32;
                if (idx < WX) {
                    int s = idx / 6, i = idx % 6;
                    int gs = base + sg * SPG + s;
                    xr[r] = (gs < NT) ? x[((size_t)gs * T + t + 1) * 6 + i] : 0.f;
                }
            }
        }

        // -------- layer 0 --------
        gemm_pass<SPG, 6, false>(sxt + cur * XN, sWih0p, aRZ, aNI, og, sg);
        gemm_pass<SPG, 64, true>(sh0 + cur * S * 64, sWhh0p, aRZ, aNH, og, sg);
#pragma unroll
        for (int p = 0; p < SPG; p++) {
            int s = sg * SPG + p;
            float r0 = siga(upk(aRZ[p][0], sbrz0[og]));
            float r1 = siga(upk(aRZ[p][1], sbrz0[32 + og]));
            float z0 = siga(upk(aRZ[p][2], sbrz0[64 + og]));
            float z1 = siga(upk(aRZ[p][3], sbrz0[96 + og]));
            float n0 = tanha(upk(aNI[p][0], sbni0[og]) + r0 * upk(aNH[p][0], sbnh0[og]));
            float n1 = tanha(upk(aNI[p][1], sbni0[32 + og]) + r1 * upk(aNH[p][1], sbnh0[32 + og]));
            float hp0 = sh0[cur * S * 64 + s * 64 + og];
            float hp1 = sh0[cur * S * 64 + s * 64 + 32 + og];
            hn0[p] = n0 + z0 * (hp0 - n0);
            hn1[p] = n1 + z1 * (hp1 - n1);
        }
#pragma unroll
        for (int p = 0; p < SPG; p++) {
            int s = sg * SPG + p;
            sh0[nxt * S * 64 + s * 64 + og] = hn0[p];
            sh0[nxt * S * 64 + s * 64 + 32 + og] = hn1[p];
        }
        if (t + 1 < T) {
#pragma unroll
            for (int r = 0; r < WXR; r++) {
                int idx = og + r * 32;
                if (idx < WX) {
                    int s = idx / 6, i = idx % 6;
                    sxt[nxt * XN + (sg * SPG + s) * 6 + i] = xr[r];
                }
            }
        }
        __syncwarp();   // intra-warp: h0[nxt] + x[nxt] visible to own warp

        // -------- layer 1: fused dual GEMM + EW --------
        gemm_dual<SPG>(sh0 + nxt * S * 64, sh1, sWih1p, sWhh1p, aRZ, aNI, aNH, og, sg);
#pragma unroll
        for (int p = 0; p < SPG; p++) {
            int s = sg * SPG + p;
            float r0 = siga(upk(aRZ[p][0], sbrz1[og]));
            float r1 = siga(upk(aRZ[p][1], sbrz1[32 + og]));
            float z0 = siga(upk(aRZ[p][2], sbrz1[64 + og]));
            float z1 = siga(upk(aRZ[p][3], sbrz1[96 + og]));
            float n0 = tanha(upk(aNI[p][0], sbni1[og]) + r0 * upk(aNH[p][0], sbnh1[og]));
            float n1 = tanha(upk(aNI[p][1], sbni1[32 + og]) + r1 * upk(aNH[p][1], sbnh1[32 + og]));
            float hp0 = sh1[s * 64 + og];
            float hp1 = sh1[s * 64 + 32 + og];
            hn0[p] = n0 + z0 * (hp0 - n0);
            hn1[p] = n1 + z1 * (hp1 - n1);
        }
        if (t == T - 1) {
#pragma unroll
            for (int p = 0; p < SPG; p++) {
                int gs = base + sg * SPG + p;
                if (gs < NT) {
                    out[(size_t)gs * 64 + og] = hn0[p];
                    out[(size_t)gs * 64 + 32 + og] = hn1[p];
                }
            }
        }
        __syncwarp();   // intra-warp: all lanes done reading sh1 before overwrite
#pragma unroll
        for (int p = 0; p < SPG; p++) {
            int s = sg * SPG + p;
            sh1[s * 64 + og] = hn0[p];
            sh1[s * 64 + 32 + og] = hn1[p];
        }
        __syncwarp();   // sh1 writes visible before next step's gemm_dual reads
    }
}

// ============================================================================
// ALSTM: j-split 2-layer GRU (unchanged; genuinely cross-warp -> syncthreads).
// ============================================================================
__global__ void __launch_bounds__(256, 1)
alstm_kernel(const float* __restrict__ zin,
             const float* __restrict__ Wih0, const float* __restrict__ Whh0,
             const float* __restrict__ bih0, const float* __restrict__ bhh0,
             const float* __restrict__ Wih1, const float* __restrict__ Whh1,
             const float* __restrict__ bih1, const float* __restrict__ bhh1,
             float* __restrict__ outr, int T)
{
    extern __shared__ float sm[];
    float* sW0   = sm;                 // [24576]
    float* sW1   = sW0 + 24576;        // [24576]
    float* sbrz0 = sW1 + 24576;        // [128]
    float* sbni0 = sbrz0 + 128;        // [64]
    float* sbnh0 = sbni0 + 64;
    float* sbrz1 = sbnh0 + 64;         // [128]
    float* sbni1 = sbrz1 + 128;
    float* sbnh1 = sbni1 + 64;         // biases end at +512
    float* sh0   = sbnh1 + 64;         // [2][256]
    float* sh1   = sh0 + 512;          // [256]
    float* sxt   = sh1 + 256;          // [2][256]
    float* sgA   = sxt + 512;          // [4][256]  layer0 gates
    float* sgB   = sgA + 1024;         // [4][256]  layer1 gates

    const int tid = threadIdx.x;
    const int base = blockIdx.x * 4;

    for (int idx = tid; idx < 24576; idx += 256) {
        int og2 = idx & 63;
        int col = idx >> 6;            // k2*12 + j*2 + src
        int src = col & 1;
        int j = (col >> 1) % 6;
        int k2 = col / 12;
        int o = j * 32 + (og2 >> 1);
        int k = k2 * 2 + (og2 & 1);
        sW0[idx] = src ? Whh0[o * 64 + k] : Wih0[o * 64 + k];
        sW1[idx] = src ? Whh1[o * 64 + k] : Wih1[o * 64 + k];
    }
    if (tid < 128) {
        sbrz0[tid] = bih0[tid] + bhh0[tid];
        sbrz1[tid] = bih1[tid] + bhh1[tid];
    } else if (tid < 192) {
        int d = tid - 128;
        sbni0[d] = bih0[128 + d]; sbnh0[d] = bhh0[128 + d];
        sbni1[d] = bih1[128 + d]; sbnh1[d] = bhh1[128 + d];
    }
    for (int idx = tid; idx < 512; idx += 256) sh0[idx] = 0.f;
    sh1[tid] = 0.f;
    {
        int s = tid >> 6, d = tid & 63;
        sxt[tid] = zin[((size_t)(base + s) * T) * 64 + d];
    }
    __syncthreads();

    const int og = tid & 31;
    const int w = tid >> 5;

    const u64* W02 = reinterpret_cast<const u64*>(sW0);
    const u64* W12 = reinterpret_cast<const u64*>(sW1);

    for (int t = 0; t < T; t++) {
        const int cur = t & 1, nxt = cur ^ 1;

        float xpre = 0.f;
        if (t + 1 < T) {
            int s = tid >> 6, d = tid & 63;
            xpre = zin[((size_t)(base + s) * T + t + 1) * 64 + d];
        }

        // ---- layer 0 GEMM (warps 0-5) ----
        if (w < 6) {
            const u64* X2 = reinterpret_cast<const u64*>(sxt + cur * 256);
            const u64* H2 = reinterpret_cast<const u64*>(sh0 + cur * 256);
            u64 aI[4] = {0, 0, 0, 0}, aH[4] = {0, 0, 0, 0};
#pragma unroll 4
            for (int k2 = 0; k2 < 32; k2++) {
                u64 wI = W02[(k2 * 12 + w * 2) * 32 + og];
                u64 wH = W02[(k2 * 12 + w * 2 + 1) * 32 + og];
#pragma unroll
                for (int s = 0; s < 4; s++) {
                    fma2(aI[s], X2[s * 32 + k2], wI);
                    fma2(aH[s], H2[s * 32 + k2], wH);
                }
            }
#pragma unroll
            for (int s = 0; s < 4; s++) {
                if (w < 4) {
                    sgA[s * 256 + w * 32 + og] = upk(aI[s], 0.f) + upk(aH[s], sbrz0[w * 32 + og]);
                } else {
                    sgA[s * 256 + 128 + (w - 4) * 32 + og] = upk(aI[s], sbni0[(w - 4) * 32 + og]);
                    sgA[s * 256 + 192 + (w - 4) * 32 + og] = upk(aH[s], sbnh0[(w - 4) * 32 + og]);
                }
            }
        }
        if (t + 1 < T) sxt[nxt * 256 + tid] = xpre;
        __syncthreads();   // B1

        // ---- layer 0 EW (warps 0-3, warp = sample) ----
        if (w < 4) {
            const float* g = sgA + w * 256;
            float r0 = sige(g[og]),       r1 = sige(g[32 + og]);
            float z0 = sige(g[64 + og]),  z1 = sige(g[96 + og]);
            float n0 = tanhe(g[128 + og] + r0 * g[192 + og]);
            float n1 = tanhe(g[160 + og] + r1 * g[224 + og]);
            float hp0 = sh0[cur * 256 + w * 64 + og];
            float hp1 = sh0[cur * 256 + w * 64 + 32 + og];
            sh0[nxt * 256 + w * 64 + og]      = n0 + z0 * (hp0 - n0);
            sh0[nxt * 256 + w * 64 + 32 + og] = n1 + z1 * (hp1 - n1);
        }
        __syncthreads();   // B2

        // ---- layer 1 GEMM (warps 0-5) ----
        if (w < 6) {
            const u64* X2 = reinterpret_cast<const u64*>(sh0 + nxt * 256);
            const u64* H2 = reinterpret_cast<const u64*>(sh1);
            u64 aI[4] = {0, 0, 0, 0}, aH[4] = {0, 0, 0, 0};
#pragma unroll 4
            for (int k2 = 0; k2 < 32; k2++) {
                u64 wI = W12[(k2 * 12 + w * 2) * 32 + og];
                u64 wH = W12[(k2 * 12 + w * 2 + 1) * 32 + og];
#pragma unroll
                for (int s = 0; s < 4; s++) {
                    fma2(aI[s], X2[s * 32 + k2], wI);
                    fma2(aH[s], H2[s * 32 + k2], wH);
                }
            }
#pragma unroll
            for (int s = 0; s < 4; s++) {
                if (w < 4) {
                    sgB[s * 256 + w * 32 + og] = upk(aI[s], 0.f) + upk(aH[s], sbrz1[w * 32 + og]);
                } else {
                    sgB[s * 256 + 128 + (w - 4) * 32 + og] = upk(aI[s], sbni1[(w - 4) * 32 + og]);
                    sgB[s * 256 + 192 + (w - 4) * 32 + og] = upk(aH[s], sbnh1[(w - 4) * 32 + og]);
                }
            }
        }
        __syncthreads();   // B3

        // ---- layer 1 EW + output (warps 0-3) ----
        if (w < 4) {
            const float* g = sgB + w * 256;
            float r0 = sige(g[og]),       r1 = sige(g[32 + og]);
            float z0 = sige(g[64 + og]),  z1 = sige(g[96 + og]);
            float n0 = tanhe(g[128 + og] + r0 * g[192 + og]);
            float n1 = tanhe(g[160 + og] + r1 * g[224 + og]);
            float hp0 = sh1[w * 64 + og];
            float hp1 = sh1[w * 64 + 32 + og];
            float h0n = n0 + z0 * (hp0 - n0);
            float h1n = n1 + z1 * (hp1 - n1);
            outr[((size_t)(base + w) * T + t) * 64 + og]      = h0n;
            outr[((size_t)(base + w) * T + t) * 64 + 32 + og] = h1n;
            sh1[w * 64 + og] = h0n;
            sh1[w * 64 + 32 + og] = h1n;
        }
        // safe: next readers of sh1 (layer-1 GEMM of t+1) sit behind B1+B2
    }
}

// v_dst = trans_W^T a[:64], v_src = trans_W^T a[64:], plus bias dots.
__global__ void prep_kernel(const float* __restrict__ tW, const float* __restrict__ tb,
                            const float* __restrict__ a)
{
    int d = threadIdx.x;  // 64 threads
    float vd = 0.f, vs = 0.f;
    for (int o = 0; o < 64; o++) {
        vd = fmaf(tW[o * 64 + d], a[o], vd);
        vs = fmaf(tW[o * 64 + d], a[64 + o], vs);
    }
    g_vec[d] = vd; g_vec[64 + d] = vs;
    if (d == 0) {
        float cd = 0.f, cs = 0.f;
        for (int o = 0; o < 64; o++) { cd = fmaf(tb[o], a[o], cd); cs = fmaf(tb[o], a[64 + o], cs); }
        g_vec[128] = cd; g_vec[129] = cs;
    }
}

// Dense GAT: per-node scores (fused) + attention + aggregate + residual.
// grid = KG*4 (group x 128-row chunk). R5 inner loop; ew buffer 1024/warp.
__global__ void att_kernel()
{
    extern __shared__ float sm[];
    float* sh  = sm;                 // [512*64] plain rows
    float* sd  = sm + 32768;         // [512] s_dst
    float* ssc = sd + 512;           // [512] s_src
    float* sv  = ssc + 512;          // [132]
    float* se  = sv + 132;           // [8 warps][8 rows][128] exp rows
    int k = blockIdx.x >> 2, chunk = blockIdx.x & 3;
    int tid = threadIdx.x, l = tid & 31, w = tid >> 5;
    const float* hg = g_hlast + (size_t)k * 512 * 64;
    for (int i = tid; i < 32768; i += 256) sh[i] = hg[i];
    if (tid < 130) sv[tid] = g_vec[tid];
    __syncthreads();

    // scores for all 512 nodes: warp w owns nodes [w*64, w*64+64)
    for (int i = 0; i < 64; i++) {
        int n = w * 64 + i;
        float h0 = sh[n * 64 + l], h1 = sh[n * 64 + 32 + l];
        float ps = h0 * sv[64 + l] + h1 * sv[96 + l];
        float pd = h0 * sv[l] + h1 * sv[32 + l];
#pragma unroll
        for (int off = 16; off; off >>= 1) {
            ps += __shfl_xor_sync(~0u, ps, off);
            pd += __shfl_xor_sync(~0u, pd, off);
        }
        if (l == 0) { ssc[n] = ps + sv[129]; sd[n] = pd + sv[128]; }
    }
    __syncthreads();

    // group max of s_dst (lrelu monotone -> row max = lrelu(s_src_i + dmax))
    float dm = -1e30f;
    for (int i = l; i < 512; i += 32) dm = fmaxf(dm, sd[i]);
#pragma unroll
    for (int off = 16; off; off >>= 1) dm = fmaxf(dm, __shfl_xor_sync(~0u, dm, off));

    const u64* sh2 = reinterpret_cast<const u64*>(sh);
    float* ew = se + w * 1024;

    for (int batch = 0; batch < 2; batch++) {
        int b0 = chunk * 128 + w * 16 + batch * 8;
        float si[8], mi[8], den[8];
        u64 acc[8];
#pragma unroll
        for (int i = 0; i < 8; i++) {
            si[i] = ssc[b0 + i];
            mi[i] = lrelu(si[i] + dm);
            den[i] = 0.f; acc[i] = 0ull;
        }
        for (int jt = 0; jt < 4; jt++) {
#pragma unroll
            for (int i = 0; i < 8; i++) {
#pragma unroll
                for (int q = 0; q < 4; q++) {
                    int j = jt * 128 + q * 32 + l;
                    float e = __expf(lrelu(si[i] + sd[j]) - mi[i]);
                    ew[i * 128 + q * 32 + l] = e;
                    den[i] += e;
                }
            }
            __syncwarp();
#pragma unroll 4
            for (int j0 = 0; j0 < 128; j0++) {
                int j = jt * 128 + j0;
                u64 hv = sh2[j * 32 + l];
#pragma unroll
                for (int i = 0; i < 8; i++) {
                    u64 e2 = (u64)__float_as_uint(ew[i * 128 + j0]);
                    e2 |= e2 << 32;
                    fma2(acc[i], e2, hv);
                }
            }
            __syncwarp();
        }
#pragma unroll
        for (int i = 0; i < 8; i++) {
            float d = den[i];
#pragma unroll
            for (int off = 16; off; off >>= 1) d += __shfl_xor_sync(~0u, d, off);
            float inv = __fdividef(1.f, d);
            int r = b0 + i;
            float* o = g_hatt + ((size_t)k * 512 + r) * 64;
            o[2 * l]     = fmaf(u64lo(acc[i]), inv, sh[r * 64 + 2 * l]);
            o[2 * l + 1] = fmaf(u64hi(acc[i]), inv, sh[r * 64 + 2 * l + 1]);
        }
    }
}

// hfc = hatt @ fc_W^T + fc_b ([m][K][64] layout); z = tanh(hfc @ al_in_W^T + al_in_b).
__global__ void fc_kernel(const float* __restrict__ fcW, const float* __restrict__ fcb,
                          const float* __restrict__ inW, const float* __restrict__ inb)
{
    __shared__ float sWf[64 * 64], sWi[64 * 64], sbf[64], sbi[64];
    __shared__ u64 sr2[8][64], sf2[8][64];
    int tid = threadIdx.x;
    for (int i = tid; i < 4096; i += 256) {
        int o = i >> 6, d = i & 63;
        sWf[d * 64 + o] = fcW[i];
        sWi[d * 64 + o] = inW[i];
    }
    if (tid < 64) { sbf[tid] = fcb[tid]; sbi[tid] = inb[tid]; }
    __syncthreads();
    const u64* sWf2 = reinterpret_cast<const u64*>(sWf);
    const u64* sWi2 = reinterpret_cast<const u64*>(sWi);
    int w = tid >> 5, l = tid & 31;
    for (int it = 0; it < 16; it++) {
        int n = blockIdx.x * 128 + it * 8 + w;  // 80*128 = 10240
        const float* hr = g_hatt + (size_t)n * 64;
        float v0 = hr[l], v1 = hr[l + 32];
        sr2[w][l] = pack2(v0, v0); sr2[w][l + 32] = pack2(v1, v1);
        __syncwarp();
        u64 acc = 0ull;
#pragma unroll 4
        for (int d = 0; d < 64; d++)
            fma2(acc, sr2[w][d], sWf2[d * 32 + l]);
        float a0 = u64lo(acc) + sbf[2 * l];
        float a1 = u64hi(acc) + sbf[2 * l + 1];
        int kk = n >> 9, ii = n & 511;
        float* of = g_hfc + ((size_t)ii * KG + kk) * 64;
        *reinterpret_cast<u64*>(&of[2 * l]) = pack2(a0, a1);
        sf2[w][2 * l] = pack2(a0, a0); sf2[w][2 * l + 1] = pack2(a1, a1);
        __syncwarp();
        u64 acc2 = 0ull;
#pragma unroll 4
        for (int d = 0; d < 64; d++)
            fma2(acc2, sf2[w][d], sWi2[d * 32 + l]);
        float z0 = tanhe(u64lo(acc2) + sbi[2 * l]);
        float z1 = tanhe(u64hi(acc2) + sbi[2 * l + 1]);
        float* oz = g_z + ((size_t)ii * KG + kk) * 64;
        *reinterpret_cast<u64*>(&oz[2 * l]) = pack2(z0, z1);
        __syncwarp();
    }
}

// ALSTM attention head + final outputs. Warp per sample. grid = 64.
__global__ void head_kernel(const float* __restrict__ W1, const float* __restrict__ b1,
                            const float* __restrict__ W2,
                            const float* __restrict__ Wo, const float* __restrict__ bo,
                            const float* __restrict__ fcoW, const float* __restrict__ fcob,
                            float* __restrict__ out)
{
    __shared__ float sW1[64 * 32], sb1[32], sW2[32], sWo[128], sfw[64];
    __shared__ float rbuf[8][64], sbuf[8][20];
    int tid = threadIdx.x;
    for (int i = tid; i < 2048; i += 256) { int o = i >> 6, d = i & 63; sW1[d * 32 + o] = W1[i]; }
    if (tid < 32) { sb1[tid] = b1[tid]; sW2[tid] = W2[tid]; }
    if (tid < 128) sWo[tid] = Wo[tid];
    if (tid < 64) sfw[tid] = fcoW[tid];
    __syncthreads();
    int w = tid >> 5, l = tid & 31;
    int n = blockIdx.x * 8 + w;
    const float* rn = g_r + (size_t)n * KG * 64;

    for (int k = 0; k < KG; k++) {
        rbuf[w][l] = rn[k * 64 + l]; rbuf[w][l + 32] = rn[k * 64 + l + 32];
        __syncwarp();
        float acc = sb1[l];
        for (int d = 0; d < 64; d++) acc = fmaf(rbuf[w][d], sW1[d * 32 + l], acc);
        float p = tanhe(acc) * sW2[l];
#pragma unroll
        for (int off = 16; off; off >>= 1) p += __shfl_xor_sync(~0u, p, off);
        if (l == 0) sbuf[w][k] = p;
        __syncwarp();
    }
    float sv = (l < KG) ? sbuf[w][l] : -1e30f;
    float mx = sv;
#pragma unroll
    for (int off = 16; off; off >>= 1) mx = fmaxf(mx, __shfl_xor_sync(~0u, mx, off));
    float e = (l < KG) ? __expf(sv - mx) : 0.f;
    float ssum = e;
#pragma unroll
    for (int off = 16; off; off >>= 1) ssum += __shfl_xor_sync(~0u, ssum, off);
    if (l < KG) sbuf[w][l] = __fdividef(e, ssum);
    __syncwarp();

    float a0 = 0.f, a1 = 0.f;
    for (int k = 0; k < KG; k++) {
        float wk = sbuf[w][k];
        a0 = fmaf(wk, rn[k * 64 + l], a0);
        a1 = fmaf(wk, rn[k * 64 + l + 32], a1);
    }
    float rl0 = rn[19 * 64 + l], rl1 = rn[19 * 64 + l + 32];
    float part = rl0 * sWo[l] + rl1 * sWo[l + 32] + a0 * sWo[64 + l] + a1 * sWo[96 + l];
#pragma unroll
    for (int off = 16; off; off >>= 1) part += __shfl_xor_sync(~0u, part, off);
    if (l == 0) out[n] = part + bo[0];

    const float* hf = g_hfc + (size_t)n * KG * 64 + 19 * 64;
    float pp = lrelu(hf[l]) * sfw[l] + lrelu(hf[l + 32]) * sfw[l + 32];
#pragma unroll
    for (int off = 16; off; off >>= 1) pp += __shfl_xor_sync(~0u, pp, off);
    if (l == 0) out[512 + n] = pp + fcob[0];
}

extern "C" void kernel_launch(void* const* d_in, const int* in_sizes, int n_in,
                              void* d_out, int out_size)
{
    const float* x      = (const float*)d_in[0];
    const float* Wih0   = (const float*)d_in[1];
    const float* Whh0   = (const float*)d_in[2];
    const float* bih0   = (const float*)d_in[3];
    const float* bhh0   = (const float*)d_in[4];
    const float* Wih1   = (const float*)d_in[5];
    const float* Whh1   = (const float*)d_in[6];
    const float* bih1   = (const float*)d_in[7];
    const float* bhh1   = (const float*)d_in[8];
    const float* transW = (const float*)d_in[9];
    const float* transb = (const float*)d_in[10];
    const float* avec   = (const float*)d_in[11];
    const float* fcW    = (const float*)d_in[12];
    const float* fcb    = (const float*)d_in[13];
    const float* fcoW   = (const float*)d_in[14];
    const float* fcob   = (const float*)d_in[15];
    const float* inW    = (const float*)d_in[16];
    const float* inb    = (const float*)d_in[17];
    const float* aWih0  = (const float*)d_in[18];
    const float* aWhh0  = (const float*)d_in[19];
    const float* abih0  = (const float*)d_in[20];
    const float* abhh0  = (const float*)d_in[21];
    const float* aWih1  = (const float*)d_in[22];
    const float* aWhh1  = (const float*)d_in[23];
    const float* abih1  = (const float*)d_in[24];
    const float* abhh1  = (const float*)d_in[25];
    const float* att1W  = (const float*)d_in[26];
    const float* att1b  = (const float*)d_in[27];
    const float* att2W  = (const float*)d_in[28];
    const float* outW   = (const float*)d_in[29];
    const float* outb   = (const float*)d_in[30];
    float* out = (float*)d_out;

    void *p_hlast, *p_z, *p_r;
    cudaGetSymbolAddress(&p_hlast, g_hlast);
    cudaGetSymbolAddress(&p_z, g_z);
    cudaGetSymbolAddress(&p_r, g_r);

    constexpr int SPG = 9, S = 8 * SPG;               // 72 samples/block, 256 thr
    const size_t smemE = (size_t)(1152 + 3 * 12288 + 512 + 2 * S * 64 + S * 64 + 2 * S * 6) * 4;
    const size_t smemA = (size_t)(2 * 24576 + 512 + 512 + 256 + 512 + 2048) * 4;
    const size_t smemAtt = (size_t)(32768 + 512 + 512 + 132 + 8 * 1024) * 4;

    cudaFuncSetAttribute(enc_kernel<SPG>,
                         cudaFuncAttributeMaxDynamicSharedMemorySize, (int)smemE);
    cudaFuncSetAttribute(alstm_kernel,
                         cudaFuncAttributeMaxDynamicSharedMemorySize, (int)smemA);
    cudaFuncSetAttribute(att_kernel,
                         cudaFuncAttributeMaxDynamicSharedMemorySize, (int)smemAtt);

    // ---- prep (idempotent; repeated to keep enc_kernel at the profiled
    //      launch slot for ncu visibility) ----
    prep_kernel<<<1, 64>>>(transW, transb, avec);
    prep_kernel<<<1, 64>>>(transW, transb, avec);
    prep_kernel<<<1, 64>>>(transW, transb, avec);

    // ---- encoder: one wave of 143 blocks x 72 samples, free-running warps ----
    enc_kernel<SPG><<<(NT + S - 1) / S, 256, smemE>>>(
        x, Wih0, Whh0, bih0, bhh0, Wih1, Whh1, bih1, bhh1,
        (float*)p_hlast, 60);

    // ---- GAT attention (scores fused in) ----
    att_kernel<<<KG * 4, 256, smemAtt>>>();

    // ---- fc + al_in tanh ----
    fc_kernel<<<80, 256>>>(fcW, fcb, inW, inb);

    // ---- ALSTM: j-split fused 2-layer GRU over K=20, batch 512 ----
    alstm_kernel<<<128, 256, smemA>>>(
        (const float*)p_z, aWih0, aWhh0, abih0, abhh0, aWih1, aWhh1, abih1, abhh1,
        (float*)p_r, 20);

    // ---- head: ALSTM attention + outputs ----
    head_kernel<<<64, 256>>>(att1W, att1b, att2W, outW, outb, fcoW, fcob, out);
}

// round 16
// speedup vs baseline: 1.1100x; 1.0133x over previous
#include <cuda_runtime.h>
#include <cstddef>

#define NT 10240
#define KG 20
#define MG 512

typedef unsigned long long u64;

// ---- scratch (device globals; allocation is forbidden) ----
__device__ float g_hlast[NT * 64];
__device__ float g_hfc[NT * 64];   // layout [m][K][64]
__device__ float g_z[NT * 64];     // layout [m][K][64]
__device__ float g_r[NT * 64];     // layout [m][K][64]
__device__ float g_vec[130];       // v_dst[64] | v_src[64] | c_dst | c_src

// exp-based (accurate) activations — used outside the encoder
__device__ __forceinline__ float sige(float v) {
    return __fdividef(1.f, 1.f + __expf(-v));
}
__device__ __forceinline__ float tanhe(float v) {
    return 1.f - __fdividef(2.f, __expf(2.f * v) + 1.f);
}
// MUFU.TANH-based (encoder only): 1 MUFU op each path
__device__ __forceinline__ float tanha(float v) {
    float r;
    asm("tanh.approx.f32 %0, %1;" : "=f"(r) : "f"(v));
    return r;
}
__device__ __forceinline__ float siga(float v) {
    return fmaf(0.5f, tanha(0.5f * v), 0.5f);
}
__device__ __forceinline__ float lrelu(float v) { return v > 0.f ? v : 0.01f * v; }

__device__ __forceinline__ void fma2(u64& d, u64 a, u64 b) {
    asm("fma.rn.f32x2 %0, %1, %2, %3;" : "=l"(d) : "l"(a), "l"(b), "l"(d));
}
__device__ __forceinline__ u64 pack2(float lo, float hi) {
    u64 r;
    asm("mov.b64 %0, {%1, %2};" : "=l"(r) : "f"(lo), "f"(hi));
    return r;
}
__device__ __forceinline__ float upk(u64 a, float bias) {
    float lo = __uint_as_float((unsigned)(a & 0xffffffffu));
    float hi = __uint_as_float((unsigned)(a >> 32));
    return lo + hi + bias;
}
__device__ __forceinline__ float u64lo(u64 a) { return __uint_as_float((unsigned)(a & 0xffffffffu)); }
__device__ __forceinline__ float u64hi(u64 a) { return __uint_as_float((unsigned)(a >> 32)); }

// ============================================================================
// ENCODER: fused 2-layer GRU, gates fully in registers. (R14 passing form)
// 256 threads / 8 warps (2/SMSP), SPG=9; free-running warps (__syncwarp only).
// ============================================================================

template <int SPG, int KDIM, bool ACCRZ>
__device__ __forceinline__ void gemm_pass(const float* __restrict__ inp,
                                          const float* __restrict__ Wp,
                                          u64 (&aRZ)[SPG][4], u64 (&aN)[SPG][2],
                                          int og, int sg)
{
    const u64* W2 = reinterpret_cast<const u64*>(Wp);
    const u64* I2 = reinterpret_cast<const u64*>(inp);
#pragma unroll
    for (int p = 0; p < SPG; p++) {
        if (!ACCRZ) { aRZ[p][0] = 0; aRZ[p][1] = 0; aRZ[p][2] = 0; aRZ[p][3] = 0; }
        aN[p][0] = 0; aN[p][1] = 0;
    }
#pragma unroll 4
    for (int k2 = 0; k2 < KDIM / 2; k2++) {
        u64 w[6];
#pragma unroll
        for (int j = 0; j < 6; j++) w[j] = W2[(k2 * 6 + j) * 32 + og];
#pragma unroll
        for (int p = 0; p < SPG; p++) {
            u64 a = I2[(sg * SPG + p) * (KDIM / 2) + k2];
            fma2(aRZ[p][0], a, w[0]);
            fma2(aRZ[p][1], a, w[1]);
            fma2(aRZ[p][2], a, w[2]);
            fma2(aRZ[p][3], a, w[3]);
            fma2(aN[p][0], a, w[4]);
            fma2(aN[p][1], a, w[5]);
        }
    }
}

template <int SPG>
__device__ __forceinline__ void gemm_dual(const float* __restrict__ inA,
                                          const float* __restrict__ inB,
                                          const float* __restrict__ WA,
                                          const float* __restrict__ WB,
                                          u64 (&aRZ)[SPG][4], u64 (&aNI)[SPG][2],
                                          u64 (&aNH)[SPG][2], int og, int sg)
{
    const u64* WA2 = reinterpret_cast<const u64*>(WA);
    const u64* WB2 = reinterpret_cast<const u64*>(WB);
    const u64* IA2 = reinterpret_cast<const u64*>(inA);
    const u64* IB2 = reinterpret_cast<const u64*>(inB);
#pragma unroll
    for (int p = 0; p < SPG; p++) {
        aRZ[p][0] = 0; aRZ[p][1] = 0; aRZ[p][2] = 0; aRZ[p][3] = 0;
        aNI[p][0] = 0; aNI[p][1] = 0; aNH[p][0] = 0; aNH[p][1] = 0;
    }
#pragma unroll 2
    for (int k2 = 0; k2 < 32; k2++) {
        u64 wa[6], wb[6];
#pragma unroll
        for (int j = 0; j < 6; j++) {
            wa[j] = WA2[(k2 * 6 + j) * 32 + og];
            wb[j] = WB2[(k2 * 6 + j) * 32 + og];
        }
#pragma unroll
        for (int p = 0; p < SPG; p++) {
            u64 a = IA2[(sg * SPG + p) * 32 + k2];
            u64 b = IB2[(sg * SPG + p) * 32 + k2];
            fma2(aRZ[p][0], a, wa[0]); fma2(aRZ[p][0], b, wb[0]);
            fma2(aRZ[p][1], a, wa[1]); fma2(aRZ[p][1], b, wb[1]);
            fma2(aRZ[p][2], a, wa[2]); fma2(aRZ[p][2], b, wb[2]);
            fma2(aRZ[p][3], a, wa[3]); fma2(aRZ[p][3], b, wb[3]);
            fma2(aNI[p][0], a, wa[4]); fma2(aNI[p][1], a, wa[5]);
            fma2(aNH[p][0], b, wb[4]); fma2(aNH[p][1], b, wb[5]);
        }
    }
}

template <int SPG>
__global__ void __launch_bounds__(256, 1)
enc_kernel(const float* __restrict__ x,
           const float* __restrict__ Wih0, const float* __restrict__ Whh0,
           const float* __restrict__ bih0, const float* __restrict__ bhh0,
           const float* __restrict__ Wih1, const float* __restrict__ Whh1,
           const float* __restrict__ bih1, const float* __restrict__ bhh1,
           float* __restrict__ out, int T)
{
    constexpr int S = 8 * SPG;
    extern __shared__ float sm[];
    float* sWih0p = sm;                      // [3*6*64]   K=6 paired
    float* sWhh0p = sWih0p + 1152;           // [32*6*64]  paired
    float* sWih1p = sWhh0p + 12288;
    float* sWhh1p = sWih1p + 12288;
    float* sbrz0  = sWhh1p + 12288;          // [128] bih0+bhh0 (r,z)
    float* sbni0  = sbrz0 + 128;             // [64]
    float* sbnh0  = sbni0 + 64;              // [64]
    float* sbrz1  = sbnh0 + 64;              // [128]
    float* sbni1  = sbrz1 + 128;
    float* sbnh1  = sbni1 + 64;
    float* sh0    = sbnh1 + 64;              // [2][S*64] double buffered
    float* sh1    = sh0 + 2 * S * 64;        // [S*64]
    float* sxt    = sh1 + S * 64;            // [2][S*6]

    const int tid = threadIdx.x;
    const int base = blockIdx.x * S;

    for (int idx = tid; idx < 12288; idx += 256) {
        int og2 = idx & 63;
        int j = (idx >> 6) % 6;
        int k2 = idx / 384;
        int o = j * 32 + (og2 >> 1);
        int k = k2 * 2 + (og2 & 1);
        sWhh0p[idx] = Whh0[o * 64 + k];
        sWih1p[idx] = Wih1[o * 64 + k];
        sWhh1p[idx] = Whh1[o * 64 + k];
    }
    for (int idx = tid; idx < 1152; idx += 256) {
        int og2 = idx & 63;
        int j = (idx >> 6) % 6;
        int k2 = idx / 384;     // < 3
        int o = j * 32 + (og2 >> 1);
        int k = k2 * 2 + (og2 & 1);
        sWih0p[idx] = Wih0[o * 6 + k];
    }
    if (tid < 128) {
        sbrz0[tid] = bih0[tid] + bhh0[tid];
        sbrz1[tid] = bih1[tid] + bhh1[tid];
    } else if (tid < 192) {
        int d = tid - 128;
        sbni0[d] = bih0[128 + d]; sbnh0[d] = bhh0[128 + d];
        sbni1[d] = bih1[128 + d]; sbnh1[d] = bhh1[128 + d];
    }
    for (int idx = tid; idx < 2 * S * 64; idx += 256) sh0[idx] = 0.f;
    for (int idx = tid; idx < S * 64; idx += 256) sh1[idx] = 0.f;
    for (int idx = tid; idx < S * 6; idx += 256) {
        int s = idx / 6, i = idx % 6;
        int gs = base + s;
        sxt[idx] = (gs < NT) ? x[((size_t)gs * T) * 6 + i] : 0.f;
    }
    __syncthreads();   // ONE barrier: weights/biases/initial state visible

    const int og = tid & 31, sg = tid >> 5;
    constexpr int XN = S * 6;
    constexpr int WX = SPG * 6;
    constexpr int WXR = (WX + 31) / 32;

    u64 aRZ[SPG][4], aNI[SPG][2], aNH[SPG][2];
    float hn0[SPG], hn1[SPG];

    for (int t = 0; t < T; t++) {
        const int cur = t & 1, nxt = cur ^ 1;

        float xr[WXR];
        if (t + 1 < T) {
#pragma unroll
            for (int r = 0; r < WXR; r++) {
                int idx = og + r * 32;
                if (idx < WX) {
                    int s = idx / 6, i = idx % 6;
                    int gs = base + sg * SPG + s;
                    xr[r] = (gs < NT) ? x[((size_t)gs * T + t + 1) * 6 + i] : 0.f;
                }
            }
        }

        // -------- layer 0 --------
        gemm_pass<SPG, 6, false>(sxt + cur * XN, sWih0p, aRZ, aNI, og, sg);
        gemm_pass<SPG, 64, true>(sh0 + cur * S * 64, sWhh0p, aRZ, aNH, og, sg);
#pragma unroll
        for (int p = 0; p < SPG; p++) {
            int s = sg * SPG + p;
            float r0 = siga(upk(aRZ[p][0], sbrz0[og]));
            float r1 = siga(upk(aRZ[p][1], sbrz0[32 + og]));
            float z0 = siga(upk(aRZ[p][2], sbrz0[64 + og]));
            float z1 = siga(upk(aRZ[p][3], sbrz0[96 + og]));
            float n0 = tanha(upk(aNI[p][0], sbni0[og]) + r0 * upk(aNH[p][0], sbnh0[og]));
            float n1 = tanha(upk(aNI[p][1], sbni0[32 + og]) + r1 * upk(aNH[p][1], sbnh0[32 + og]));
            float hp0 = sh0[cur * S * 64 + s * 64 + og];
            float hp1 = sh0[cur * S * 64 + s * 64 + 32 + og];
            hn0[p] = n0 + z0 * (hp0 - n0);
            hn1[p] = n1 + z1 * (hp1 - n1);
        }
#pragma unroll
        for (int p = 0; p < SPG; p++) {
            int s = sg * SPG + p;
            sh0[nxt * S * 64 + s * 64 + og] = hn0[p];
            sh0[nxt * S * 64 + s * 64 + 32 + og] = hn1[p];
        }
        if (t + 1 < T) {
#pragma unroll
            for (int r = 0; r < WXR; r++) {
                int idx = og + r * 32;
                if (idx < WX) {
                    int s = idx / 6, i = idx % 6;
                    sxt[nxt * XN + (sg * SPG + s) * 6 + i] = xr[r];
                }
            }
        }
        __syncwarp();

        // -------- layer 1: fused dual GEMM + EW --------
        gemm_dual<SPG>(sh0 + nxt * S * 64, sh1, sWih1p, sWhh1p, aRZ, aNI, aNH, og, sg);
#pragma unroll
        for (int p = 0; p < SPG; p++) {
            int s = sg * SPG + p;
            float r0 = siga(upk(aRZ[p][0], sbrz1[og]));
            float r1 = siga(upk(aRZ[p][1], sbrz1[32 + og]));
            float z0 = siga(upk(aRZ[p][2], sbrz1[64 + og]));
            float z1 = siga(upk(aRZ[p][3], sbrz1[96 + og]));
            float n0 = tanha(upk(aNI[p][0], sbni1[og]) + r0 * upk(aNH[p][0], sbnh1[og]));
            float n1 = tanha(upk(aNI[p][1], sbni1[32 + og]) + r1 * upk(aNH[p][1], sbnh1[32 + og]));
            float hp0 = sh1[s * 64 + og];
            float hp1 = sh1[s * 64 + 32 + og];
            hn0[p] = n0 + z0 * (hp0 - n0);
            hn1[p] = n1 + z1 * (hp1 - n1);
        }
        if (t == T - 1) {
#pragma unroll
            for (int p = 0; p < SPG; p++) {
                int gs = base + sg * SPG + p;
                if (gs < NT) {
                    out[(size_t)gs * 64 + og] = hn0[p];
                    out[(size_t)gs * 64 + 32 + og] = hn1[p];
                }
            }
        }
        __syncwarp();
#pragma unroll
        for (int p = 0; p < SPG; p++) {
            int s = sg * SPG + p;
            sh1[s * 64 + og] = hn0[p];
            sh1[s * 64 + 32 + og] = hn1[p];
        }
        __syncwarp();
    }
}

// ============================================================================
// ALSTM: j-split 2-layer GRU (unchanged from R14 passing kernel).
// ============================================================================
__global__ void __launch_bounds__(256, 1)
alstm_kernel(const float* __restrict__ zin,
             const float* __restrict__ Wih0, const float* __restrict__ Whh0,
             const float* __restrict__ bih0, const float* __restrict__ bhh0,
             const float* __restrict__ Wih1, const float* __restrict__ Whh1,
             const float* __restrict__ bih1, const float* __restrict__ bhh1,
             float* __restrict__ outr, int T)
{
    extern __shared__ float sm[];
    float* sW0   = sm;                 // [24576]
    float* sW1   = sW0 + 24576;        // [24576]
    float* sbrz0 = sW1 + 24576;        // [128]
    float* sbni0 = sbrz0 + 128;        // [64]
    float* sbnh0 = sbni0 + 64;
    float* sbrz1 = sbnh0 + 64;         // [128]
    float* sbni1 = sbrz1 + 128;
    float* sbnh1 = sbni1 + 64;         // biases end at +512
    float* sh0   = sbnh1 + 64;         // [2][256]
    float* sh1   = sh0 + 512;          // [256]
    float* sxt   = sh1 + 256;          // [2][256]
    float* sgA   = sxt + 512;          // [4][256]  layer0 gates
    float* sgB   = sgA + 1024;         // [4][256]  layer1 gates

    const int tid = threadIdx.x;
    const int base = blockIdx.x * 4;

    for (int idx = tid; idx < 24576; idx += 256) {
        int og2 = idx & 63;
        int col = idx >> 6;            // k2*12 + j*2 + src
        int src = col & 1;
        int j = (col >> 1) % 6;
        int k2 = col / 12;
        int o = j * 32 + (og2 >> 1);
        int k = k2 * 2 + (og2 & 1);
        sW0[idx] = src ? Whh0[o * 64 + k] : Wih0[o * 64 + k];
        sW1[idx] = src ? Whh1[o * 64 + k] : Wih1[o * 64 + k];
    }
    if (tid < 128) {
        sbrz0[tid] = bih0[tid] + bhh0[tid];
        sbrz1[tid] = bih1[tid] + bhh1[tid];
    } else if (tid < 192) {
        int d = tid - 128;
        sbni0[d] = bih0[128 + d]; sbnh0[d] = bhh0[128 + d];
        sbni1[d] = bih1[128 + d]; sbnh1[d] = bhh1[128 + d];
    }
    for (int idx = tid; idx < 512; idx += 256) sh0[idx] = 0.f;
    sh1[tid] = 0.f;
    {
        int s = tid >> 6, d = tid & 63;
        sxt[tid] = zin[((size_t)(base + s) * T) * 64 + d];
    }
    __syncthreads();

    const int og = tid & 31;
    const int w = tid >> 5;

    const u64* W02 = reinterpret_cast<const u64*>(sW0);
    const u64* W12 = reinterpret_cast<const u64*>(sW1);

    for (int t = 0; t < T; t++) {
        const int cur = t & 1, nxt = cur ^ 1;

        float xpre = 0.f;
        if (t + 1 < T) {
            int s = tid >> 6, d = tid & 63;
            xpre = zin[((size_t)(base + s) * T + t + 1) * 64 + d];
        }

        // ---- layer 0 GEMM (warps 0-5) ----
        if (w < 6) {
            const u64* X2 = reinterpret_cast<const u64*>(sxt + cur * 256);
            const u64* H2 = reinterpret_cast<const u64*>(sh0 + cur * 256);
            u64 aI[4] = {0, 0, 0, 0}, aH[4] = {0, 0, 0, 0};
#pragma unroll 4
            for (int k2 = 0; k2 < 32; k2++) {
                u64 wI = W02[(k2 * 12 + w * 2) * 32 + og];
                u64 wH = W02[(k2 * 12 + w * 2 + 1) * 32 + og];
#pragma unroll
                for (int s = 0; s < 4; s++) {
                    fma2(aI[s], X2[s * 32 + k2], wI);
                    fma2(aH[s], H2[s * 32 + k2], wH);
                }
            }
#pragma unroll
            for (int s = 0; s < 4; s++) {
                if (w < 4) {
                    sgA[s * 256 + w * 32 + og] = upk(aI[s], 0.f) + upk(aH[s], sbrz0[w * 32 + og]);
                } else {
                    sgA[s * 256 + 128 + (w - 4) * 32 + og] = upk(aI[s], sbni0[(w - 4) * 32 + og]);
                    sgA[s * 256 + 192 + (w - 4) * 32 + og] = upk(aH[s], sbnh0[(w - 4) * 32 + og]);
                }
            }
        }
        if (t + 1 < T) sxt[nxt * 256 + tid] = xpre;
        __syncthreads();   // B1

        // ---- layer 0 EW (warps 0-3, warp = sample) ----
        if (w < 4) {
            const float* g = sgA + w * 256;
            float r0 = sige(g[og]),       r1 = sige(g[32 + og]);
            float z0 = sige(g[64 + og]),  z1 = sige(g[96 + og]);
            float n0 = tanhe(g[128 + og] + r0 * g[192 + og]);
            float n1 = tanhe(g[160 + og] + r1 * g[224 + og]);
            float hp0 = sh0[cur * 256 + w * 64 + og];
            float hp1 = sh0[cur * 256 + w * 64 + 32 + og];
            sh0[nxt * 256 + w * 64 + og]      = n0 + z0 * (hp0 - n0);
            sh0[nxt * 256 + w * 64 + 32 + og] = n1 + z1 * (hp1 - n1);
        }
        __syncthreads();   // B2

        // ---- layer 1 GEMM (warps 0-5) ----
        if (w < 6) {
            const u64* X2 = reinterpret_cast<const u64*>(sh0 + nxt * 256);
            const u64* H2 = reinterpret_cast<const u64*>(sh1);
            u64 aI[4] = {0, 0, 0, 0}, aH[4] = {0, 0, 0, 0};
#pragma unroll 4
            for (int k2 = 0; k2 < 32; k2++) {
                u64 wI = W12[(k2 * 12 + w * 2) * 32 + og];
                u64 wH = W12[(k2 * 12 + w * 2 + 1) * 32 + og];
#pragma unroll
                for (int s = 0; s < 4; s++) {
                    fma2(aI[s], X2[s * 32 + k2], wI);
                    fma2(aH[s], H2[s * 32 + k2], wH);
                }
            }
#pragma unroll
            for (int s = 0; s < 4; s++) {
                if (w < 4) {
                    sgB[s * 256 + w * 32 + og] = upk(aI[s], 0.f) + upk(aH[s], sbrz1[w * 32 + og]);
                } else {
                    sgB[s * 256 + 128 + (w - 4) * 32 + og] = upk(aI[s], sbni1[(w - 4) * 32 + og]);
                    sgB[s * 256 + 192 + (w - 4) * 32 + og] = upk(aH[s], sbnh1[(w - 4) * 32 + og]);
                }
            }
        }
        __syncthreads();   // B3

        // ---- layer 1 EW + output (warps 0-3) ----
        if (w < 4) {
            const float* g = sgB + w * 256;
            float r0 = sige(g[og]),       r1 = sige(g[32 + og]);
            float z0 = sige(g[64 + og]),  z1 = sige(g[96 + og]);
            float n0 = tanhe(g[128 + og] + r0 * g[192 + og]);
            float n1 = tanhe(g[160 + og] + r1 * g[224 + og]);
            float hp0 = sh1[w * 64 + og];
            float hp1 = sh1[w * 64 + 32 + og];
            float h0n = n0 + z0 * (hp0 - n0);
            float h1n = n1 + z1 * (hp1 - n1);
            outr[((size_t)(base + w) * T + t) * 64 + og]      = h0n;
            outr[((size_t)(base + w) * T + t) * 64 + 32 + og] = h1n;
            sh1[w * 64 + og] = h0n;
            sh1[w * 64 + 32 + og] = h1n;
        }
        // safe: next readers of sh1 (layer-1 GEMM of t+1) sit behind B1+B2
    }
}

// v_dst = trans_W^T a[:64], v_src = trans_W^T a[64:], plus bias dots.
__global__ void prep_kernel(const float* __restrict__ tW, const float* __restrict__ tb,
                            const float* __restrict__ a)
{
    int d = threadIdx.x;  // 64 threads
    float vd = 0.f, vs = 0.f;
    for (int o = 0; o < 64; o++) {
        vd = fmaf(tW[o * 64 + d], a[o], vd);
        vs = fmaf(tW[o * 64 + d], a[64 + o], vs);
    }
    g_vec[d] = vd; g_vec[64 + d] = vs;
    if (d == 0) {
        float cd = 0.f, cs = 0.f;
        for (int o = 0; o < 64; o++) { cd = fmaf(tb[o], a[o], cd); cs = fmaf(tb[o], a[64 + o], cs); }
        g_vec[128] = cd; g_vec[129] = cs;
    }
}

// ============================================================================
// Dense GAT + fc + al_in (FUSED): per-node scores + attention + aggregate +
// residual + fc GEMM -> g_hfc + tanh(al_in GEMM) -> g_z.
// grid = KG*4 (group x 128-row chunk). ew buffer (1024 f / 512 u64 per warp)
// is reused as duplicated-u64 staging for the f32x2 row GEMMs.
// ============================================================================
__global__ void att_kernel(const float* __restrict__ fcW, const float* __restrict__ fcb,
                           const float* __restrict__ inW, const float* __restrict__ inb)
{
    extern __shared__ float sm[];
    float* sh   = sm;                  // [32768] h rows
    float* sd   = sh + 32768;          // [512] s_dst
    float* ssc  = sd + 512;            // [512] s_src
    float* sv   = ssc + 512;           // [132]
    float* se   = sv + 132;            // [8 warps][1024] exp rows / dup staging
    float* sWf  = se + 8192;           // [4096] fc_W transposed
    float* sWi  = sWf + 4096;          // [4096] al_in_W transposed
    float* sbf  = sWi + 4096;          // [64]
    float* sbi  = sbf + 64;            // [64]
    u64*  dup2  = reinterpret_cast<u64*>(sbi + 64);  // [8 warps][64] u64

    int k = blockIdx.x >> 2, chunk = blockIdx.x & 3;
    int tid = threadIdx.x, l = tid & 31, w = tid >> 5;
    const float* hg = g_hlast + (size_t)k * 512 * 64;
    for (int i = tid; i < 32768; i += 256) sh[i] = hg[i];
    if (tid < 130) sv[tid] = g_vec[tid];
    for (int i = tid; i < 4096; i += 256) {
        int o = i >> 6, d = i & 63;
        sWf[d * 64 + o] = fcW[i];
        sWi[d * 64 + o] = inW[i];
    }
    if (tid < 64) { sbf[tid] = fcb[tid]; sbi[tid] = inb[tid]; }
    __syncthreads();

    // scores for all 512 nodes: warp w owns nodes [w*64, w*64+64)
    for (int i = 0; i < 64; i++) {
        int n = w * 64 + i;
        float h0 = sh[n * 64 + l], h1 = sh[n * 64 + 32 + l];
        float ps = h0 * sv[64 + l] + h1 * sv[96 + l];
        float pd = h0 * sv[l] + h1 * sv[32 + l];
#pragma unroll
        for (int off = 16; off; off >>= 1) {
            ps += __shfl_xor_sync(~0u, ps, off);
            pd += __shfl_xor_sync(~0u, pd, off);
        }
        if (l == 0) { ssc[n] = ps + sv[129]; sd[n] = pd + sv[128]; }
    }
    __syncthreads();

    // group max of s_dst (lrelu monotone -> row max = lrelu(s_src_i + dmax))
    float dm = -1e30f;
    for (int i = l; i < 512; i += 32) dm = fmaxf(dm, sd[i]);
#pragma unroll
    for (int off = 16; off; off >>= 1) dm = fmaxf(dm, __shfl_xor_sync(~0u, dm, off));

    const u64* sh2 = reinterpret_cast<const u64*>(sh);
    const u64* sWf2 = reinterpret_cast<const u64*>(sWf);
    const u64* sWi2 = reinterpret_cast<const u64*>(sWi);
    float* ew = se + w * 1024;
    u64* dupU = reinterpret_cast<u64*>(ew);   // 512 u64, reused post-aggregation
    u64* myd2 = dup2 + w * 64;

    for (int batch = 0; batch < 2; batch++) {
        int b0 = chunk * 128 + w * 16 + batch * 8;
        float si[8], mi[8], den[8];
        u64 acc[8];
#pragma unroll
        for (int i = 0; i < 8; i++) {
            si[i] = ssc[b0 + i];
            mi[i] = lrelu(si[i] + dm);
            den[i] = 0.f; acc[i] = 0ull;
        }
        for (int jt = 0; jt < 4; jt++) {
#pragma unroll
            for (int i = 0; i < 8; i++) {
#pragma unroll
                for (int q = 0; q < 4; q++) {
                    int j = jt * 128 + q * 32 + l;
                    float e = __expf(lrelu(si[i] + sd[j]) - mi[i]);
                    ew[i * 128 + q * 32 + l] = e;
                    den[i] += e;
                }
            }
            __syncwarp();
#pragma unroll 4
            for (int j0 = 0; j0 < 128; j0++) {
                int j = jt * 128 + j0;
                u64 hv = sh2[j * 32 + l];
#pragma unroll
                for (int i = 0; i < 8; i++) {
                    u64 e2 = (u64)__float_as_uint(ew[i * 128 + j0]);
                    e2 |= e2 << 32;
                    fma2(acc[i], e2, hv);
                }
            }
            __syncwarp();
        }

        // ---- epilogue: residual + fc + al_in for this batch's 8 rows ----
        // stage duplicated hatt rows into dupU (ew memory, now free)
#pragma unroll
        for (int i = 0; i < 8; i++) {
            float d = den[i];
#pragma unroll
            for (int off = 16; off; off >>= 1) d += __shfl_xor_sync(~0u, d, off);
            float inv = __fdividef(1.f, d);
            int r = b0 + i;
            float a0 = fmaf(u64lo(acc[i]), inv, sh[r * 64 + 2 * l]);
            float a1 = fmaf(u64hi(acc[i]), inv, sh[r * 64 + 2 * l + 1]);
            dupU[i * 64 + 2 * l]     = pack2(a0, a0);
            dupU[i * 64 + 2 * l + 1] = pack2(a1, a1);
        }
        __syncwarp();

        for (int i = 0; i < 8; i++) {
            int rr = b0 + i;                 // m index within group
            // fc GEMM: lane owns outputs (2l, 2l+1)
            u64 accf = 0ull;
#pragma unroll 4
            for (int d = 0; d < 64; d++)
                fma2(accf, dupU[i * 64 + d], sWf2[d * 32 + l]);
            float f0 = u64lo(accf) + sbf[2 * l];
            float f1 = u64hi(accf) + sbf[2 * l + 1];
            float* of = g_hfc + ((size_t)rr * KG + k) * 64;
            *reinterpret_cast<u64*>(&of[2 * l]) = pack2(f0, f1);
            myd2[2 * l]     = pack2(f0, f0);
            myd2[2 * l + 1] = pack2(f1, f1);
            __syncwarp();
            // al_in GEMM + tanh
            u64 acci = 0ull;
#pragma unroll 4
            for (int d = 0; d < 64; d++)
                fma2(acci, myd2[d], sWi2[d * 32 + l]);
            float z0 = tanhe(u64lo(acci) + sbi[2 * l]);
            float z1 = tanhe(u64hi(acci) + sbi[2 * l + 1]);
            float* oz = g_z + ((size_t)rr * KG + k) * 64;
            *reinterpret_cast<u64*>(&oz[2 * l]) = pack2(z0, z1);
            __syncwarp();
        }
    }
}

// ALSTM attention head + final outputs. Warp per sample. grid = 64.
__global__ void head_kernel(const float* __restrict__ W1, const float* __restrict__ b1,
                            const float* __restrict__ W2,
                            const float* __restrict__ Wo, const float* __restrict__ bo,
                            const float* __restrict__ fcoW, const float* __restrict__ fcob,
                            float* __restrict__ out)
{
    __shared__ float sW1[64 * 32], sb1[32], sW2[32], sWo[128], sfw[64];
    __shared__ float rbuf[8][64], sbuf[8][20];
    int tid = threadIdx.x;
    for (int i = tid; i < 2048; i += 256) { int o = i >> 6, d = i & 63; sW1[d * 32 + o] = W1[i]; }
    if (tid < 32) { sb1[tid] = b1[tid]; sW2[tid] = W2[tid]; }
    if (tid < 128) sWo[tid] = Wo[tid];
    if (tid < 64) sfw[tid] = fcoW[tid];
    __syncthreads();
    int w = tid >> 5, l = tid & 31;
    int n = blockIdx.x * 8 + w;
    const float* rn = g_r + (size_t)n * KG * 64;

    for (int k = 0; k < KG; k++) {
        rbuf[w][l] = rn[k * 64 + l]; rbuf[w][l + 32] = rn[k * 64 + l + 32];
        __syncwarp();
        float acc = sb1[l];
        for (int d = 0; d < 64; d++) acc = fmaf(rbuf[w][d], sW1[d * 32 + l], acc);
        float p = tanhe(acc) * sW2[l];
#pragma unroll
        for (int off = 16; off; off >>= 1) p += __shfl_xor_sync(~0u, p, off);
        if (l == 0) sbuf[w][k] = p;
        __syncwarp();
    }
    float sv = (l < KG) ? sbuf[w][l] : -1e30f;
    float mx = sv;
#pragma unroll
    for (int off = 16; off; off >>= 1) mx = fmaxf(mx, __shfl_xor_sync(~0u, mx, off));
    float e = (l < KG) ? __expf(sv - mx) : 0.f;
    float ssum = e;
#pragma unroll
    for (int off = 16; off; off >>= 1) ssum += __shfl_xor_sync(~0u, ssum, off);
    if (l < KG) sbuf[w][l] = __fdividef(e, ssum);
    __syncwarp();

    float a0 = 0.f, a1 = 0.f;
    for (int k = 0; k < KG; k++) {
        float wk = sbuf[w][k];
        a0 = fmaf(wk, rn[k * 64 + l], a0);
        a1 = fmaf(wk, rn[k * 64 + l + 32], a1);
    }
    float rl0 = rn[19 * 64 + l], rl1 = rn[19 * 64 + l + 32];
    float part = rl0 * sWo[l] + rl1 * sWo[l + 32] + a0 * sWo[64 + l] + a1 * sWo[96 + l];
#pragma unroll
    for (int off = 16; off; off >>= 1) part += __shfl_xor_sync(~0u, part, off);
    if (l == 0) out[n] = part + bo[0];

    const float* hf = g_hfc + (size_t)n * KG * 64 + 19 * 64;
    float pp = lrelu(hf[l]) * sfw[l] + lrelu(hf[l + 32]) * sfw[l + 32];
#pragma unroll
    for (int off = 16; off; off >>= 1) pp += __shfl_xor_sync(~0u, pp, off);
    if (l == 0) out[512 + n] = pp + fcob[0];
}

extern "C" void kernel_launch(void* const* d_in, const int* in_sizes, int n_in,
                              void* d_out, int out_size)
{
    const float* x      = (const float*)d_in[0];
    const float* Wih0   = (const float*)d_in[1];
    const float* Whh0   = (const float*)d_in[2];
    const float* bih0   = (const float*)d_in[3];
    const float* bhh0   = (const float*)d_in[4];
    const float* Wih1   = (const float*)d_in[5];
    const float* Whh1   = (const float*)d_in[6];
    const float* bih1   = (const float*)d_in[7];
    const float* bhh1   = (const float*)d_in[8];
    const float* transW = (const float*)d_in[9];
    const float* transb = (const float*)d_in[10];
    const float* avec   = (const float*)d_in[11];
    const float* fcW    = (const float*)d_in[12];
    const float* fcb    = (const float*)d_in[13];
    const float* fcoW   = (const float*)d_in[14];
    const float* fcob   = (const float*)d_in[15];
    const float* inW    = (const float*)d_in[16];
    const float* inb    = (const float*)d_in[17];
    const float* aWih0  = (const float*)d_in[18];
    const float* aWhh0  = (const float*)d_in[19];
    const float* abih0  = (const float*)d_in[20];
    const float* abhh0  = (const float*)d_in[21];
    const float* aWih1  = (const float*)d_in[22];
    const float* aWhh1  = (const float*)d_in[23];
    const float* abih1  = (const float*)d_in[24];
    const float* abhh1  = (const float*)d_in[25];
    const float* att1W  = (const float*)d_in[26];
    const float* att1b  = (const float*)d_in[27];
    const float* att2W  = (const float*)d_in[28];
    const float* outW   = (const float*)d_in[29];
    const float* outb   = (const float*)d_in[30];
    float* out = (float*)d_out;

    void *p_hlast, *p_z, *p_r;
    cudaGetSymbolAddress(&p_hlast, g_hlast);
    cudaGetSymbolAddress(&p_z, g_z);
    cudaGetSymbolAddress(&p_r, g_r);

    constexpr int SPG = 9, S = 8 * SPG;               // 72 samples/block, 256 thr
    const size_t smemE = (size_t)(1152 + 3 * 12288 + 512 + 2 * S * 64 + S * 64 + 2 * S * 6) * 4;
    const size_t smemA = (size_t)(2 * 24576 + 512 + 512 + 256 + 512 + 2048) * 4;
    // att: 32768 + 512 + 512 + 132 + 8192 + 4096 + 4096 + 64 + 64 floats + 8*64 u64
    const size_t smemAtt = (size_t)(32768 + 512 + 512 + 132 + 8192 + 4096 + 4096 + 64 + 64) * 4
                         + (size_t)8 * 64 * 8;

    cudaFuncSetAttribute(enc_kernel<SPG>,
                         cudaFuncAttributeMaxDynamicSharedMemorySize, (int)smemE);
    cudaFuncSetAttribute(alstm_kernel,
                         cudaFuncAttributeMaxDynamicSharedMemorySize, (int)smemA);
    cudaFuncSetAttribute(att_kernel,
                         cudaFuncAttributeMaxDynamicSharedMemorySize, (int)smemAtt);

    // ---- prep (idempotent; repeated to keep enc_kernel at the profiled
    //      launch slot for ncu visibility) ----
    prep_kernel<<<1, 64>>>(transW, transb, avec);
    prep_kernel<<<1, 64>>>(transW, transb, avec);
    prep_kernel<<<1, 64>>>(transW, transb, avec);

    // ---- encoder: one wave of 143 blocks x 72 samples, free-running warps ----
    enc_kernel<SPG><<<(NT + S - 1) / S, 256, smemE>>>(
        x, Wih0, Whh0, bih0, bhh0, Wih1, Whh1, bih1, bhh1,
        (float*)p_hlast, 60);

    // ---- GAT attention + fc + al_in (fused) ----
    att_kernel<<<KG * 4, 256, smemAtt>>>(fcW, fcb, inW, inb);

    // ---- ALSTM: j-split fused 2-layer GRU over K=20, batch 512 ----
    alstm_kernel<<<128, 256, smemA>>>(
        (const float*)p_z, aWih0, aWhh0, abih0, abhh0, aWih1, aWhh1, abih1, abhh1,
        (float*)p_r, 20);

    // ---- head: ALSTM attention + outputs ----
    head_kernel<<<64, 256>>>(att1W, att1b, att2W, outW, outb, fcoW, fcob, out);
}

// round 17
// speedup vs baseline: 1.1226x; 1.0114x over previous
#include <cuda_runtime.h>
#include <cstddef>

#define NT 10240
#define KG 20
#define MG 512

typedef unsigned long long u64;

// ---- scratch (device globals; allocation is forbidden) ----
__device__ float g_hlast[NT * 64];
__device__ float g_hfc[NT * 64];   // layout [m][K][64]
__device__ float g_z[NT * 64];     // layout [m][K][64]
__device__ float g_r[NT * 64];     // layout [m][K][64]
__device__ float g_vec[130];       // v_dst[64] | v_src[64] | c_dst | c_src

// exp-based (accurate) activations — used outside the encoder
__device__ __forceinline__ float sige(float v) {
    return __fdividef(1.f, 1.f + __expf(-v));
}
__device__ __forceinline__ float tanhe(float v) {
    return 1.f - __fdividef(2.f, __expf(2.f * v) + 1.f);
}
// MUFU.TANH-based (encoder only): 1 MUFU op each path
__device__ __forceinline__ float tanha(float v) {
    float r;
    asm("tanh.approx.f32 %0, %1;" : "=f"(r) : "f"(v));
    return r;
}
__device__ __forceinline__ float siga(float v) {
    return fmaf(0.5f, tanha(0.5f * v), 0.5f);
}
__device__ __forceinline__ float lrelu(float v) { return v > 0.f ? v : 0.01f * v; }

__device__ __forceinline__ void fma2(u64& d, u64 a, u64 b) {
    asm("fma.rn.f32x2 %0, %1, %2, %3;" : "=l"(d) : "l"(a), "l"(b), "l"(d));
}
__device__ __forceinline__ u64 pack2(float lo, float hi) {
    u64 r;
    asm("mov.b64 %0, {%1, %2};" : "=l"(r) : "f"(lo), "f"(hi));
    return r;
}
__device__ __forceinline__ float upk(u64 a, float bias) {
    float lo = __uint_as_float((unsigned)(a & 0xffffffffu));
    float hi = __uint_as_float((unsigned)(a >> 32));
    return lo + hi + bias;
}
__device__ __forceinline__ float u64lo(u64 a) { return __uint_as_float((unsigned)(a & 0xffffffffu)); }
__device__ __forceinline__ float u64hi(u64 a) { return __uint_as_float((unsigned)(a >> 32)); }

// ============================================================================
// ENCODER: fused 2-layer GRU, gates fully in registers. (unchanged)
// 256 threads / 8 warps (2/SMSP), SPG=9; free-running warps (__syncwarp only).
// ============================================================================

template <int SPG, int KDIM, bool ACCRZ>
__device__ __forceinline__ void gemm_pass(const float* __restrict__ inp,
                                          const float* __restrict__ Wp,
                                          u64 (&aRZ)[SPG][4], u64 (&aN)[SPG][2],
                                          int og, int sg)
{
    const u64* W2 = reinterpret_cast<const u64*>(Wp);
    const u64* I2 = reinterpret_cast<const u64*>(inp);
#pragma unroll
    for (int p = 0; p < SPG; p++) {
        if (!ACCRZ) { aRZ[p][0] = 0; aRZ[p][1] = 0; aRZ[p][2] = 0; aRZ[p][3] = 0; }
        aN[p][0] = 0; aN[p][1] = 0;
    }
#pragma unroll 4
    for (int k2 = 0; k2 < KDIM / 2; k2++) {
        u64 w[6];
#pragma unroll
        for (int j = 0; j < 6; j++) w[j] = W2[(k2 * 6 + j) * 32 + og];
#pragma unroll
        for (int p = 0; p < SPG; p++) {
            u64 a = I2[(sg * SPG + p) * (KDIM / 2) + k2];
            fma2(aRZ[p][0], a, w[0]);
            fma2(aRZ[p][1], a, w[1]);
            fma2(aRZ[p][2], a, w[2]);
            fma2(aRZ[p][3], a, w[3]);
            fma2(aN[p][0], a, w[4]);
            fma2(aN[p][1], a, w[5]);
        }
    }
}

template <int SPG>
__device__ __forceinline__ void gemm_dual(const float* __restrict__ inA,
                                          const float* __restrict__ inB,
                                          const float* __restrict__ WA,
                                          const float* __restrict__ WB,
                                          u64 (&aRZ)[SPG][4], u64 (&aNI)[SPG][2],
                                          u64 (&aNH)[SPG][2], int og, int sg)
{
    const u64* WA2 = reinterpret_cast<const u64*>(WA);
    const u64* WB2 = reinterpret_cast<const u64*>(WB);
    const u64* IA2 = reinterpret_cast<const u64*>(inA);
    const u64* IB2 = reinterpret_cast<const u64*>(inB);
#pragma unroll
    for (int p = 0; p < SPG; p++) {
        aRZ[p][0] = 0; aRZ[p][1] = 0; aRZ[p][2] = 0; aRZ[p][3] = 0;
        aNI[p][0] = 0; aNI[p][1] = 0; aNH[p][0] = 0; aNH[p][1] = 0;
    }
#pragma unroll 2
    for (int k2 = 0; k2 < 32; k2++) {
        u64 wa[6], wb[6];
#pragma unroll
        for (int j = 0; j < 6; j++) {
            wa[j] = WA2[(k2 * 6 + j) * 32 + og];
            wb[j] = WB2[(k2 * 6 + j) * 32 + og];
        }
#pragma unroll
        for (int p = 0; p < SPG; p++) {
            u64 a = IA2[(sg * SPG + p) * 32 + k2];
            u64 b = IB2[(sg * SPG + p) * 32 + k2];
            fma2(aRZ[p][0], a, wa[0]); fma2(aRZ[p][0], b, wb[0]);
            fma2(aRZ[p][1], a, wa[1]); fma2(aRZ[p][1], b, wb[1]);
            fma2(aRZ[p][2], a, wa[2]); fma2(aRZ[p][2], b, wb[2]);
            fma2(aRZ[p][3], a, wa[3]); fma2(aRZ[p][3], b, wb[3]);
            fma2(aNI[p][0], a, wa[4]); fma2(aNI[p][1], a, wa[5]);
            fma2(aNH[p][0], b, wb[4]); fma2(aNH[p][1], b, wb[5]);
        }
    }
}

template <int SPG>
__global__ void __launch_bounds__(256, 1)
enc_kernel(const float* __restrict__ x,
           const float* __restrict__ Wih0, const float* __restrict__ Whh0,
           const float* __restrict__ bih0, const float* __restrict__ bhh0,
           const float* __restrict__ Wih1, const float* __restrict__ Whh1,
           const float* __restrict__ bih1, const float* __restrict__ bhh1,
           float* __restrict__ out, int T)
{
    constexpr int S = 8 * SPG;
    extern __shared__ float sm[];
    float* sWih0p = sm;                      // [3*6*64]   K=6 paired
    float* sWhh0p = sWih0p + 1152;           // [32*6*64]  paired
    float* sWih1p = sWhh0p + 12288;
    float* sWhh1p = sWih1p + 12288;
    float* sbrz0  = sWhh1p + 12288;          // [128] bih0+bhh0 (r,z)
    float* sbni0  = sbrz0 + 128;             // [64]
    float* sbnh0  = sbni0 + 64;              // [64]
    float* sbrz1  = sbnh0 + 64;              // [128]
    float* sbni1  = sbrz1 + 128;
    float* sbnh1  = sbni1 + 64;
    float* sh0    = sbnh1 + 64;              // [2][S*64] double buffered
    float* sh1    = sh0 + 2 * S * 64;        // [S*64]
    float* sxt    = sh1 + S * 64;            // [2][S*6]

    const int tid = threadIdx.x;
    const int base = blockIdx.x * S;

    for (int idx = tid; idx < 12288; idx += 256) {
        int og2 = idx & 63;
        int j = (idx >> 6) % 6;
        int k2 = idx / 384;
        int o = j * 32 + (og2 >> 1);
        int k = k2 * 2 + (og2 & 1);
        sWhh0p[idx] = Whh0[o * 64 + k];
        sWih1p[idx] = Wih1[o * 64 + k];
        sWhh1p[idx] = Whh1[o * 64 + k];
    }
    for (int idx = tid; idx < 1152; idx += 256) {
        int og2 = idx & 63;
        int j = (idx >> 6) % 6;
        int k2 = idx / 384;     // < 3
        int o = j * 32 + (og2 >> 1);
        int k = k2 * 2 + (og2 & 1);
        sWih0p[idx] = Wih0[o * 6 + k];
    }
    if (tid < 128) {
        sbrz0[tid] = bih0[tid] + bhh0[tid];
        sbrz1[tid] = bih1[tid] + bhh1[tid];
    } else if (tid < 192) {
        int d = tid - 128;
        sbni0[d] = bih0[128 + d]; sbnh0[d] = bhh0[128 + d];
        sbni1[d] = bih1[128 + d]; sbnh1[d] = bhh1[128 + d];
    }
    for (int idx = tid; idx < 2 * S * 64; idx += 256) sh0[idx] = 0.f;
    for (int idx = tid; idx < S * 64; idx += 256) sh1[idx] = 0.f;
    for (int idx = tid; idx < S * 6; idx += 256) {
        int s = idx / 6, i = idx % 6;
        int gs = base + s;
        sxt[idx] = (gs < NT) ? x[((size_t)gs * T) * 6 + i] : 0.f;
    }
    __syncthreads();   // ONE barrier: weights/biases/initial state visible

    const int og = tid & 31, sg = tid >> 5;
    constexpr int XN = S * 6;
    constexpr int WX = SPG * 6;
    constexpr int WXR = (WX + 31) / 32;

    u64 aRZ[SPG][4], aNI[SPG][2], aNH[SPG][2];
    float hn0[SPG], hn1[SPG];

    for (int t = 0; t < T; t++) {
        const int cur = t & 1, nxt = cur ^ 1;

        float xr[WXR];
        if (t + 1 < T) {
#pragma unroll
            for (int r = 0; r < WXR; r++) {
                int idx = og + r * 32;
                if (idx < WX) {
                    int s = idx / 6, i = idx % 6;
                    int gs = base + sg * SPG + s;
                    xr[r] = (gs < NT) ? x[((size_t)gs * T + t + 1) * 6 + i] : 0.f;
                }
            }
        }

        // -------- layer 0 --------
        gemm_pass<SPG, 6, false>(sxt + cur * XN, sWih0p, aRZ, aNI, og, sg);
        gemm_pass<SPG, 64, true>(sh0 + cur * S * 64, sWhh0p, aRZ, aNH, og, sg);
#pragma unroll
        for (int p = 0; p < SPG; p++) {
            int s = sg * SPG + p;
            float r0 = siga(upk(aRZ[p][0], sbrz0[og]));
            float r1 = siga(upk(aRZ[p][1], sbrz0[32 + og]));
            float z0 = siga(upk(aRZ[p][2], sbrz0[64 + og]));
            float z1 = siga(upk(aRZ[p][3], sbrz0[96 + og]));
            float n0 = tanha(upk(aNI[p][0], sbni0[og]) + r0 * upk(aNH[p][0], sbnh0[og]));
            float n1 = tanha(upk(aNI[p][1], sbni0[32 + og]) + r1 * upk(aNH[p][1], sbnh0[32 + og]));
            float hp0 = sh0[cur * S * 64 + s * 64 + og];
            float hp1 = sh0[cur * S * 64 + s * 64 + 32 + og];
            hn0[p] = n0 + z0 * (hp0 - n0);
            hn1[p] = n1 + z1 * (hp1 - n1);
        }
#pragma unroll
        for (int p = 0; p < SPG; p++) {
            int s = sg * SPG + p;
            sh0[nxt * S * 64 + s * 64 + og] = hn0[p];
            sh0[nxt * S * 64 + s * 64 + 32 + og] = hn1[p];
        }
        if (t + 1 < T) {
#pragma unroll
            for (int r = 0; r < WXR; r++) {
                int idx = og + r * 32;
                if (idx < WX) {
                    int s = idx / 6, i = idx % 6;
                    sxt[nxt * XN + (sg * SPG + s) * 6 + i] = xr[r];
                }
            }
        }
        __syncwarp();

        // -------- layer 1: fused dual GEMM + EW --------
        gemm_dual<SPG>(sh0 + nxt * S * 64, sh1, sWih1p, sWhh1p, aRZ, aNI, aNH, og, sg);
#pragma unroll
        for (int p = 0; p < SPG; p++) {
            int s = sg * SPG + p;
            float r0 = siga(upk(aRZ[p][0], sbrz1[og]));
            float r1 = siga(upk(aRZ[p][1], sbrz1[32 + og]));
            float z0 = siga(upk(aRZ[p][2], sbrz1[64 + og]));
            float z1 = siga(upk(aRZ[p][3], sbrz1[96 + og]));
            float n0 = tanha(upk(aNI[p][0], sbni1[og]) + r0 * upk(aNH[p][0], sbnh1[og]));
            float n1 = tanha(upk(aNI[p][1], sbni1[32 + og]) + r1 * upk(aNH[p][1], sbnh1[32 + og]));
            float hp0 = sh1[s * 64 + og];
            float hp1 = sh1[s * 64 + 32 + og];
            hn0[p] = n0 + z0 * (hp0 - n0);
            hn1[p] = n1 + z1 * (hp1 - n1);
        }
        if (t == T - 1) {
#pragma unroll
            for (int p = 0; p < SPG; p++) {
                int gs = base + sg * SPG + p;
                if (gs < NT) {
                    out[(size_t)gs * 64 + og] = hn0[p];
                    out[(size_t)gs * 64 + 32 + og] = hn1[p];
                }
            }
        }
        __syncwarp();
#pragma unroll
        for (int p = 0; p < SPG; p++) {
            int s = sg * SPG + p;
            sh1[s * 64 + og] = hn0[p];
            sh1[s * 64 + 32 + og] = hn1[p];
        }
        __syncwarp();
    }
}

// ============================================================================
// ALSTM + HEAD (FUSED): j-split 2-layer GRU over K=20, then per-sample
// attention head + final outputs in the same block. EW-warp w owns sample
// base+w in BOTH phases; lane l reads back exactly the g_r elements it wrote
// (visibility via block-scope __syncthreads ordering of global accesses).
// grid = 128 blocks x 4 samples.
// ============================================================================
__global__ void __launch_bounds__(256, 1)
alstm_kernel(const float* __restrict__ zin,
             const float* __restrict__ Wih0, const float* __restrict__ Whh0,
             const float* __restrict__ bih0, const float* __restrict__ bhh0,
             const float* __restrict__ Wih1, const float* __restrict__ Whh1,
             const float* __restrict__ bih1, const float* __restrict__ bhh1,
             float* __restrict__ outr, int T,
             const float* __restrict__ W1, const float* __restrict__ b1,
             const float* __restrict__ W2,
             const float* __restrict__ Wo, const float* __restrict__ bo,
             const float* __restrict__ fcoW, const float* __restrict__ fcob,
             float* __restrict__ outv)
{
    extern __shared__ float sm[];
    float* sW0   = sm;                 // [24576]
    float* sW1g  = sW0 + 24576;        // [24576]
    float* sbrz0 = sW1g + 24576;       // [128]
    float* sbni0 = sbrz0 + 128;        // [64]
    float* sbnh0 = sbni0 + 64;
    float* sbrz1 = sbnh0 + 64;         // [128]
    float* sbni1 = sbrz1 + 128;
    float* sbnh1 = sbni1 + 64;         // biases end at +512
    float* sh0   = sbnh1 + 64;         // [2][256]
    float* sh1   = sh0 + 512;          // [256]
    float* sxt   = sh1 + 256;          // [2][256]
    float* sgA   = sxt + 512;          // [4][256]  layer0 gates / head staging
    float* sgB   = sgA + 1024;         // [4][256]  layer1 gates / head p-buffer
    float* sW1h  = sgB + 1024;         // [2048] att1_W transposed
    float* sb1h  = sW1h + 2048;        // [32]
    float* sW2h  = sb1h + 32;          // [32]
    float* sWoh  = sW2h + 32;          // [128]
    float* sfwh  = sWoh + 128;         // [64]

    const int tid = threadIdx.x;
    const int base = blockIdx.x * 4;

    for (int idx = tid; idx < 24576; idx += 256) {
        int og2 = idx & 63;
        int col = idx >> 6;            // k2*12 + j*2 + src
        int src = col & 1;
        int j = (col >> 1) % 6;
        int k2 = col / 12;
        int o = j * 32 + (og2 >> 1);
        int k = k2 * 2 + (og2 & 1);
        sW0[idx] = src ? Whh0[o * 64 + k] : Wih0[o * 64 + k];
        sW1g[idx] = src ? Whh1[o * 64 + k] : Wih1[o * 64 + k];
    }
    for (int i = tid; i < 2048; i += 256) {
        int o = i >> 6, d = i & 63;
        sW1h[d * 32 + o] = W1[i];
    }
    if (tid < 128) {
        sbrz0[tid] = bih0[tid] + bhh0[tid];
        sbrz1[tid] = bih1[tid] + bhh1[tid];
        sWoh[tid] = Wo[tid];
    } else if (tid < 192) {
        int d = tid - 128;
        sbni0[d] = bih0[128 + d]; sbnh0[d] = bhh0[128 + d];
        sbni1[d] = bih1[128 + d]; sbnh1[d] = bhh1[128 + d];
        sfwh[d] = fcoW[d];
    } else if (tid < 224) {
        int d = tid - 192;
        sb1h[d] = b1[d]; sW2h[d] = W2[d];
    }
    for (int idx = tid; idx < 512; idx += 256) sh0[idx] = 0.f;
    sh1[tid] = 0.f;
    {
        int s = tid >> 6, d = tid & 63;
        sxt[tid] = zin[((size_t)(base + s) * T) * 64 + d];
    }
    __syncthreads();

    const int og = tid & 31;
    const int w = tid >> 5;

    const u64* W02 = reinterpret_cast<const u64*>(sW0);
    const u64* W12 = reinterpret_cast<const u64*>(sW1g);

    for (int t = 0; t < T; t++) {
        const int cur = t & 1, nxt = cur ^ 1;

        float xpre = 0.f;
        if (t + 1 < T) {
            int s = tid >> 6, d = tid & 63;
            xpre = zin[((size_t)(base + s) * T + t + 1) * 64 + d];
        }

        // ---- layer 0 GEMM (warps 0-5) ----
        if (w < 6) {
            const u64* X2 = reinterpret_cast<const u64*>(sxt + cur * 256);
            const u64* H2 = reinterpret_cast<const u64*>(sh0 + cur * 256);
            u64 aI[4] = {0, 0, 0, 0}, aH[4] = {0, 0, 0, 0};
#pragma unroll 4
            for (int k2 = 0; k2 < 32; k2++) {
                u64 wI = W02[(k2 * 12 + w * 2) * 32 + og];
                u64 wH = W02[(k2 * 12 + w * 2 + 1) * 32 + og];
#pragma unroll
                for (int s = 0; s < 4; s++) {
                    fma2(aI[s], X2[s * 32 + k2], wI);
                    fma2(aH[s], H2[s * 32 + k2], wH);
                }
            }
#pragma unroll
            for (int s = 0; s < 4; s++) {
                if (w < 4) {
                    sgA[s * 256 + w * 32 + og] = upk(aI[s], 0.f) + upk(aH[s], sbrz0[w * 32 + og]);
                } else {
                    sgA[s * 256 + 128 + (w - 4) * 32 + og] = upk(aI[s], sbni0[(w - 4) * 32 + og]);
                    sgA[s * 256 + 192 + (w - 4) * 32 + og] = upk(aH[s], sbnh0[(w - 4) * 32 + og]);
                }
            }
        }
        if (t + 1 < T) sxt[nxt * 256 + tid] = xpre;
        __syncthreads();   // B1

        // ---- layer 0 EW (warps 0-3, warp = sample) ----
        if (w < 4) {
            const float* g = sgA + w * 256;
            float r0 = sige(g[og]),       r1 = sige(g[32 + og]);
            float z0 = sige(g[64 + og]),  z1 = sige(g[96 + og]);
            float n0 = tanhe(g[128 + og] + r0 * g[192 + og]);
            float n1 = tanhe(g[160 + og] + r1 * g[224 + og]);
            float hp0 = sh0[cur * 256 + w * 64 + og];
            float hp1 = sh0[cur * 256 + w * 64 + 32 + og];
            sh0[nxt * 256 + w * 64 + og]      = n0 + z0 * (hp0 - n0);
            sh0[nxt * 256 + w * 64 + 32 + og] = n1 + z1 * (hp1 - n1);
        }
        __syncthreads();   // B2

        // ---- layer 1 GEMM (warps 0-5) ----
        if (w < 6) {
            const u64* X2 = reinterpret_cast<const u64*>(sh0 + nxt * 256);
            const u64* H2 = reinterpret_cast<const u64*>(sh1);
            u64 aI[4] = {0, 0, 0, 0}, aH[4] = {0, 0, 0, 0};
#pragma unroll 4
            for (int k2 = 0; k2 < 32; k2++) {
                u64 wI = W12[(k2 * 12 + w * 2) * 32 + og];
                u64 wH = W12[(k2 * 12 + w * 2 + 1) * 32 + og];
#pragma unroll
                for (int s = 0; s < 4; s++) {
                    fma2(aI[s], X2[s * 32 + k2], wI);
                    fma2(aH[s], H2[s * 32 + k2], wH);
                }
            }
#pragma unroll
            for (int s = 0; s < 4; s++) {
                if (w < 4) {
                    sgB[s * 256 + w * 32 + og] = upk(aI[s], 0.f) + upk(aH[s], sbrz1[w * 32 + og]);
                } else {
                    sgB[s * 256 + 128 + (w - 4) * 32 + og] = upk(aI[s], sbni1[(w - 4) * 32 + og]);
                    sgB[s * 256 + 192 + (w - 4) * 32 + og] = upk(aH[s], sbnh1[(w - 4) * 32 + og]);
                }
            }
        }
        __syncthreads();   // B3

        // ---- layer 1 EW + r output (warps 0-3) ----
        if (w < 4) {
            const float* g = sgB + w * 256;
            float r0 = sige(g[og]),       r1 = sige(g[32 + og]);
            float z0 = sige(g[64 + og]),  z1 = sige(g[96 + og]);
            float n0 = tanhe(g[128 + og] + r0 * g[192 + og]);
            float n1 = tanhe(g[160 + og] + r1 * g[224 + og]);
            float hp0 = sh1[w * 64 + og];
            float hp1 = sh1[w * 64 + 32 + og];
            float h0n = n0 + z0 * (hp0 - n0);
            float h1n = n1 + z1 * (hp1 - n1);
            outr[((size_t)(base + w) * T + t) * 64 + og]      = h0n;
            outr[((size_t)(base + w) * T + t) * 64 + 32 + og] = h1n;
            sh1[w * 64 + og] = h0n;
            sh1[w * 64 + 32 + og] = h1n;
        }
        // safe: next readers of sh1 (layer-1 GEMM of t+1) sit behind B1+B2
    }

    // ======================= fused head =======================
    __syncthreads();   // orders this block's g_r global writes block-wide
    if (w < 4) {
        const int l = og;
        const int n = base + w;
        const float* rn = outr + (size_t)n * KG * 64;
        float* rb = sgA + w * 256;   // 64-float staging
        float* pb = sgB + w * 256;   // 20-float p buffer

        for (int k = 0; k < KG; k++) {
            rb[l] = rn[k * 64 + l]; rb[l + 32] = rn[k * 64 + 32 + l];
            __syncwarp();
            float acc = sb1h[l];
            for (int d = 0; d < 64; d++) acc = fmaf(rb[d], sW1h[d * 32 + l], acc);
            float p = tanhe(acc) * sW2h[l];
#pragma unroll
            for (int off = 16; off; off >>= 1) p += __shfl_xor_sync(~0u, p, off);
            if (l == 0) pb[k] = p;
            __syncwarp();
        }
        float sv = (l < KG) ? pb[l] : -1e30f;
        float mx = sv;
#pragma unroll
        for (int off = 16; off; off >>= 1) mx = fmaxf(mx, __shfl_xor_sync(~0u, mx, off));
        float e = (l < KG) ? __expf(sv - mx) : 0.f;
        float ssum = e;
#pragma unroll
        for (int off = 16; off; off >>= 1) ssum += __shfl_xor_sync(~0u, ssum, off);
        if (l < KG) pb[l] = __fdividef(e, ssum);
        __syncwarp();

        float a0 = 0.f, a1 = 0.f;
        for (int k = 0; k < KG; k++) {
            float wk = pb[k];
            a0 = fmaf(wk, rn[k * 64 + l], a0);
            a1 = fmaf(wk, rn[k * 64 + 32 + l], a1);
        }
        float rl0 = rn[19 * 64 + l], rl1 = rn[19 * 64 + 32 + l];
        float part = rl0 * sWoh[l] + rl1 * sWoh[l + 32] + a0 * sWoh[64 + l] + a1 * sWoh[96 + l];
#pragma unroll
        for (int off = 16; off; off >>= 1) part += __shfl_xor_sync(~0u, part, off);
        if (l == 0) outv[n] = part + bo[0];

        const float* hf = g_hfc + (size_t)n * KG * 64 + 19 * 64;
        float pp = lrelu(hf[l]) * sfwh[l] + lrelu(hf[l + 32]) * sfwh[l + 32];
#pragma unroll
        for (int off = 16; off; off >>= 1) pp += __shfl_xor_sync(~0u, pp, off);
        if (l == 0) outv[512 + n] = pp + fcob[0];
    }
}

// v_dst = trans_W^T a[:64], v_src = trans_W^T a[64:], plus bias dots.
__global__ void prep_kernel(const float* __restrict__ tW, const float* __restrict__ tb,
                            const float* __restrict__ a)
{
    int d = threadIdx.x;  // 64 threads
    float vd = 0.f, vs = 0.f;
    for (int o = 0; o < 64; o++) {
        vd = fmaf(tW[o * 64 + d], a[o], vd);
        vs = fmaf(tW[o * 64 + d], a[64 + o], vs);
    }
    g_vec[d] = vd; g_vec[64 + d] = vs;
    if (d == 0) {
        float cd = 0.f, cs = 0.f;
        for (int o = 0; o < 64; o++) { cd = fmaf(tb[o], a[o], cd); cs = fmaf(tb[o], a[64 + o], cs); }
        g_vec[128] = cd; g_vec[129] = cs;
    }
}

// ============================================================================
// Dense GAT + fc + al_in (FUSED): unchanged from R15 passing kernel.
// ============================================================================
__global__ void att_kernel(const float* __restrict__ fcW, const float* __restrict__ fcb,
                           const float* __restrict__ inW, const float* __restrict__ inb)
{
    extern __shared__ float sm[];
    float* sh   = sm;                  // [32768] h rows
    float* sd   = sh + 32768;          // [512] s_dst
    float* ssc  = sd + 512;            // [512] s_src
    float* sv   = ssc + 512;           // [132]
    float* se   = sv + 132;            // [8 warps][1024] exp rows / dup staging
    float* sWf  = se + 8192;           // [4096] fc_W transposed
    float* sWi  = sWf + 4096;          // [4096] al_in_W transposed
    float* sbf  = sWi + 4096;          // [64]
    float* sbi  = sbf + 64;            // [64]
    u64*  dup2  = reinterpret_cast<u64*>(sbi + 64);  // [8 warps][64] u64

    int k = blockIdx.x >> 2, chunk = blockIdx.x & 3;
    int tid = threadIdx.x, l = tid & 31, w = tid >> 5;
    const float* hg = g_hlast + (size_t)k * 512 * 64;
    for (int i = tid; i < 32768; i += 256) sh[i] = hg[i];
    if (tid < 130) sv[tid] = g_vec[tid];
    for (int i = tid; i < 4096; i += 256) {
        int o = i >> 6, d = i & 63;
        sWf[d * 64 + o] = fcW[i];
        sWi[d * 64 + o] = inW[i];
    }
    if (tid < 64) { sbf[tid] = fcb[tid]; sbi[tid] = inb[tid]; }
    __syncthreads();

    // scores for all 512 nodes: warp w owns nodes [w*64, w*64+64)
    for (int i = 0; i < 64; i++) {
        int n = w * 64 + i;
        float h0 = sh[n * 64 + l], h1 = sh[n * 64 + 32 + l];
        float ps = h0 * sv[64 + l] + h1 * sv[96 + l];
        float pd = h0 * sv[l] + h1 * sv[32 + l];
#pragma unroll
        for (int off = 16; off; off >>= 1) {
            ps += __shfl_xor_sync(~0u, ps, off);
            pd += __shfl_xor_sync(~0u, pd, off);
        }
        if (l == 0) { ssc[n] = ps + sv[129]; sd[n] = pd + sv[128]; }
    }
    __syncthreads();

    // group max of s_dst (lrelu monotone -> row max = lrelu(s_src_i + dmax))
    float dm = -1e30f;
    for (int i = l; i < 512; i += 32) dm = fmaxf(dm, sd[i]);
#pragma unroll
    for (int off = 16; off; off >>= 1) dm = fmaxf(dm, __shfl_xor_sync(~0u, dm, off));

    const u64* sh2 = reinterpret_cast<const u64*>(sh);
    const u64* sWf2 = reinterpret_cast<const u64*>(sWf);
    const u64* sWi2 = reinterpret_cast<const u64*>(sWi);
    float* ew = se + w * 1024;
    u64* dupU = reinterpret_cast<u64*>(ew);   // 512 u64, reused post-aggregation
    u64* myd2 = dup2 + w * 64;

    for (int batch = 0; batch < 2; batch++) {
        int b0 = chunk * 128 + w * 16 + batch * 8;
        float si[8], mi[8], den[8];
        u64 acc[8];
#pragma unroll
        for (int i = 0; i < 8; i++) {
            si[i] = ssc[b0 + i];
            mi[i] = lrelu(si[i] + dm);
            den[i] = 0.f; acc[i] = 0ull;
        }
        for (int jt = 0; jt < 4; jt++) {
#pragma unroll
            for (int i = 0; i < 8; i++) {
#pragma unroll
                for (int q = 0; q < 4; q++) {
                    int j = jt * 128 + q * 32 + l;
                    float e = __expf(lrelu(si[i] + sd[j]) - mi[i]);
                    ew[i * 128 + q * 32 + l] = e;
                    den[i] += e;
                }
            }
            __syncwarp();
#pragma unroll 4
            for (int j0 = 0; j0 < 128; j0++) {
                int j = jt * 128 + j0;
                u64 hv = sh2[j * 32 + l];
#pragma unroll
                for (int i = 0; i < 8; i++) {
                    u64 e2 = (u64)__float_as_uint(ew[i * 128 + j0]);
                    e2 |= e2 << 32;
                    fma2(acc[i], e2, hv);
                }
            }
            __syncwarp();
        }

        // ---- epilogue: residual + fc + al_in for this batch's 8 rows ----
#pragma unroll
        for (int i = 0; i < 8; i++) {
            float d = den[i];
#pragma unroll
            for (int off = 16; off; off >>= 1) d += __shfl_xor_sync(~0u, d, off);
            float inv = __fdividef(1.f, d);
            int r = b0 + i;
            float a0 = fmaf(u64lo(acc[i]), inv, sh[r * 64 + 2 * l]);
            float a1 = fmaf(u64hi(acc[i]), inv, sh[r * 64 + 2 * l + 1]);
            dupU[i * 64 + 2 * l]     = pack2(a0, a0);
            dupU[i * 64 + 2 * l + 1] = pack2(a1, a1);
        }
        __syncwarp();

        for (int i = 0; i < 8; i++) {
            int rr = b0 + i;
            u64 accf = 0ull;
#pragma unroll 4
            for (int d = 0; d < 64; d++)
                fma2(accf, dupU[i * 64 + d], sWf2[d * 32 + l]);
            float f0 = u64lo(accf) + sbf[2 * l];
            float f1 = u64hi(accf) + sbf[2 * l + 1];
            float* of = g_hfc + ((size_t)rr * KG + k) * 64;
            *reinterpret_cast<u64*>(&of[2 * l]) = pack2(f0, f1);
            myd2[2 * l]     = pack2(f0, f0);
            myd2[2 * l + 1] = pack2(f1, f1);
            __syncwarp();
            u64 acci = 0ull;
#pragma unroll 4
            for (int d = 0; d < 64; d++)
                fma2(acci, myd2[d], sWi2[d * 32 + l]);
            float z0 = tanhe(u64lo(acci) + sbi[2 * l]);
            float z1 = tanhe(u64hi(acci) + sbi[2 * l + 1]);
            float* oz = g_z + ((size_t)rr * KG + k) * 64;
            *reinterpret_cast<u64*>(&oz[2 * l]) = pack2(z0, z1);
            __syncwarp();
        }
    }
}

extern "C" void kernel_launch(void* const* d_in, const int* in_sizes, int n_in,
                              void* d_out, int out_size)
{
    const float* x      = (const float*)d_in[0];
    const float* Wih0   = (const float*)d_in[1];
    const float* Whh0   = (const float*)d_in[2];
    const float* bih0   = (const float*)d_in[3];
    const float* bhh0   = (const float*)d_in[4];
    const float* Wih1   = (const float*)d_in[5];
    const float* Whh1   = (const float*)d_in[6];
    const float* bih1   = (const float*)d_in[7];
    const float* bhh1   = (const float*)d_in[8];
    const float* transW = (const float*)d_in[9];
    const float* transb = (const float*)d_in[10];
    const float* avec   = (const float*)d_in[11];
    const float* fcW    = (const float*)d_in[12];
    const float* fcb    = (const float*)d_in[13];
    const float* fcoW   = (const float*)d_in[14];
    const float* fcob   = (const float*)d_in[15];
    const float* inW    = (const float*)d_in[16];
    const float* inb    = (const float*)d_in[17];
    const float* aWih0  = (const float*)d_in[18];
    const float* aWhh0  = (const float*)d_in[19];
    const float* abih0  = (const float*)d_in[20];
    const float* abhh0  = (const float*)d_in[21];
    const float* aWih1  = (const float*)d_in[22];
    const float* aWhh1  = (const float*)d_in[23];
    const float* abih1  = (const float*)d_in[24];
    const float* abhh1  = (const float*)d_in[25];
    const float* att1W  = (const float*)d_in[26];
    const float* att1b  = (const float*)d_in[27];
    const float* att2W  = (const float*)d_in[28];
    const float* outW   = (const float*)d_in[29];
    const float* outb   = (const float*)d_in[30];
    float* out = (float*)d_out;

    void *p_hlast, *p_z, *p_r;
    cudaGetSymbolAddress(&p_hlast, g_hlast);
    cudaGetSymbolAddress(&p_z, g_z);
    cudaGetSymbolAddress(&p_r, g_r);

    constexpr int SPG = 9, S = 8 * SPG;               // 72 samples/block, 256 thr
    const size_t smemE = (size_t)(1152 + 3 * 12288 + 512 + 2 * S * 64 + S * 64 + 2 * S * 6) * 4;
    const size_t smemA = (size_t)(2 * 24576 + 512 + 512 + 256 + 512 + 2048
                                  + 2048 + 32 + 32 + 128 + 64) * 4;
    const size_t smemAtt = (size_t)(32768 + 512 + 512 + 132 + 8192 + 4096 + 4096 + 64 + 64) * 4
                         + (size_t)8 * 64 * 8;

    cudaFuncSetAttribute(enc_kernel<SPG>,
                         cudaFuncAttributeMaxDynamicSharedMemorySize, (int)smemE);
    cudaFuncSetAttribute(alstm_kernel,
                         cudaFuncAttributeMaxDynamicSharedMemorySize, (int)smemA);
    cudaFuncSetAttribute(att_kernel,
                         cudaFuncAttributeMaxDynamicSharedMemorySize, (int)smemAtt);

    // ---- prep ----
    prep_kernel<<<1, 64>>>(transW, transb, avec);

    // ---- encoder: one wave of 143 blocks x 72 samples, free-running warps ----
    enc_kernel<SPG><<<(NT + S - 1) / S, 256, smemE>>>(
        x, Wih0, Whh0, bih0, bhh0, Wih1, Whh1, bih1, bhh1,
        (float*)p_hlast, 60);

    // ---- GAT attention + fc + al_in (fused) ----
    att_kernel<<<KG * 4, 256, smemAtt>>>(fcW, fcb, inW, inb);

    // ---- ALSTM + head (fused): 2-layer GRU over K=20 then outputs ----
    alstm_kernel<<<128, 256, smemA>>>(
        (const float*)p_z, aWih0, aWhh0, abih0, abhh0, aWih1, aWhh1, abih1, abhh1,
        (float*)p_r, 20,
        att1W, att1b, att2W, outW, outb, fcoW, fcob, out);
}